// round 3
// baseline (speedup 1.0000x reference)
#include <cuda_runtime.h>
#include <cuda_bf16.h>

#define NP 20000
#define NC 80000
#define NN 100000
#define HIDD 128

// ---------------- scratch (static device globals; no allocation) ----------------
__device__ float g_h[(size_t)NN * HIDD];      // layer input features
__device__ float g_h2[(size_t)NN * HIDD];     // layer-1 output
__device__ float g_accum[(size_t)NN * HIDD];  // scatter accumulator
__device__ float g_cnt[NN];
__device__ float g_inv[NN];

// ---------------- helpers ----------------
__device__ __forceinline__ void red_add_v4(float* p, float4 v) {
    asm volatile("red.global.add.v4.f32 [%0], {%1,%2,%3,%4};"
                 :: "l"(p), "f"(v.x), "f"(v.y), "f"(v.z), "f"(v.w) : "memory");
}

// ---------------- degree count + reciprocal ----------------
__global__ void count_kernel(const int* __restrict__ dst, float* cnt, int E) {
    int e = blockIdx.x * blockDim.x + threadIdx.x;
    if (e < E) atomicAdd(&cnt[dst[e]], 1.0f);
}
__global__ void inv_kernel(const float* __restrict__ cnt, float* inv, int n) {
    int i = blockIdx.x * blockDim.x + threadIdx.x;
    if (i < n) inv[i] = 1.0f / fmaxf(cnt[i], 1.0f);
}

// ---------------- edge scatter: accum[dst] += h[src], warp per edge ----------------
__global__ void scatter_kernel(const float* __restrict__ h, float* __restrict__ accum,
                               const int* __restrict__ src, const int* __restrict__ dst,
                               int E) {
    int gtid = blockIdx.x * blockDim.x + threadIdx.x;
    int e = gtid >> 5;
    int lane = gtid & 31;
    if (e >= E) return;
    int s = 0, d = 0;
    if (lane == 0) { s = __ldg(&src[e]); d = __ldg(&dst[e]); }
    s = __shfl_sync(0xffffffffu, s, 0);
    d = __shfl_sync(0xffffffffu, d, 0);
    const float4 v = *(const float4*)(h + (size_t)s * HIDD + lane * 4);
    red_add_v4(accum + (size_t)d * HIDD + lane * 4, v);
}

// ---------------- encoder: out = relu(concat(x, emb1[i1], emb2[i2]) @ W + b) ----------------
// 128x128 output tile, KT=8, 256 threads, 8x8 microtile
__global__ __launch_bounds__(256) void encoder_kernel(
    const float* __restrict__ xdyn, int xdim,
    const int* __restrict__ idx1, const float* __restrict__ emb1, int e1,
    const int* __restrict__ idx2, const float* __restrict__ emb2, int e2,
    const float* __restrict__ W, const float* __restrict__ bias,
    float* __restrict__ out, int nrows)
{
    __shared__ float As[8][132];
    __shared__ float Bs[8][128];
    const int t = threadIdx.x;
    const int tx = t & 15, ty = t >> 4;
    const int row0 = blockIdx.x * 128;
    const int K = xdim + e1 + e2;

    float acc[8][8];
#pragma unroll
    for (int r = 0; r < 8; r++)
#pragma unroll
        for (int c = 0; c < 8; c++) acc[r][c] = 0.f;

    for (int k0 = 0; k0 < K; k0 += 8) {
        // stage A (gather/concat), 1024 elements
#pragma unroll
        for (int i = 0; i < 4; i++) {
            int idx = t + 256 * i;
            int k = idx & 7, r = idx >> 3;
            int row = row0 + r;
            float v = 0.f;
            if (row < nrows) {
                int kk = k0 + k;
                if (kk < xdim) v = xdyn[(size_t)row * xdim + kk];
                else if (kk < xdim + e1) v = emb1[idx1[row] * e1 + (kk - xdim)];
                else if (kk < K) v = emb2[idx2[row] * e2 + (kk - xdim - e1)];
            }
            As[k][r] = v;
        }
        // stage B, 1024 elements (coalesced)
#pragma unroll
        for (int i = 0; i < 4; i++) {
            int idx = t + 256 * i;
            int col = idx & 127, k = idx >> 7;
            float w = 0.f;
            if (k0 + k < K) w = W[(size_t)(k0 + k) * HIDD + col];
            Bs[k][col] = w;
        }
        __syncthreads();
#pragma unroll
        for (int kk = 0; kk < 8; kk++) {
            float4 a0 = *(const float4*)&As[kk][ty * 8];
            float4 a1 = *(const float4*)&As[kk][ty * 8 + 4];
            float4 b0 = *(const float4*)&Bs[kk][tx * 8];
            float4 b1 = *(const float4*)&Bs[kk][tx * 8 + 4];
            float a[8] = {a0.x, a0.y, a0.z, a0.w, a1.x, a1.y, a1.z, a1.w};
            float b[8] = {b0.x, b0.y, b0.z, b0.w, b1.x, b1.y, b1.z, b1.w};
#pragma unroll
            for (int r = 0; r < 8; r++)
#pragma unroll
                for (int c = 0; c < 8; c++) acc[r][c] = fmaf(a[r], b[c], acc[r][c]);
        }
        __syncthreads();
    }
#pragma unroll
    for (int r = 0; r < 8; r++) {
        int row = row0 + ty * 8 + r;
        if (row >= nrows) break;
        float* o = out + (size_t)row * HIDD + tx * 8;
#pragma unroll
        for (int c = 0; c < 8; c++) {
            float v = acc[r][c] + bias[tx * 8 + c];
            o[c] = fmaxf(v, 0.f);
        }
    }
}

// ---------------- fused SAGE GEMM: out = act( (accum*inv) @ Wl + bl + hin @ Wr ) ----------------
// K = 256 (128 from mean-aggregated, 128 from self), 128x128 tile, KT=16
__global__ __launch_bounds__(256) void sage_gemm_kernel(
    const float* __restrict__ hin,
    const float* __restrict__ Wl, const float* __restrict__ bl,
    const float* __restrict__ Wr,
    float* __restrict__ out, int nrows, int do_relu)
{
    __shared__ float As[16][132];
    __shared__ float Bs[16][128];
    const int t = threadIdx.x;
    const int tx = t & 15, ty = t >> 4;
    const int row0 = blockIdx.x * 128;

    float acc[8][8];
#pragma unroll
    for (int r = 0; r < 8; r++)
#pragma unroll
        for (int c = 0; c < 8; c++) acc[r][c] = 0.f;

    for (int k0 = 0; k0 < 2 * HIDD; k0 += 16) {
        const bool left = (k0 < HIDD);  // uniform per tile (128 % 16 == 0)
        // stage A: 512 float4 reads (coalesced), scattered smem writes
#pragma unroll
        for (int i = 0; i < 2; i++) {
            int idx4 = t + 256 * i;
            int k4 = idx4 & 3, r = idx4 >> 2;
            int row = row0 + r;
            float4 v = make_float4(0.f, 0.f, 0.f, 0.f);
            if (row < nrows) {
                int kk = k0 + k4 * 4;
                if (left) {
                    v = *(const float4*)(g_accum + (size_t)row * HIDD + kk);
                    float iv = g_inv[row];
                    v.x *= iv; v.y *= iv; v.z *= iv; v.w *= iv;
                } else {
                    v = *(const float4*)(hin + (size_t)row * HIDD + (kk - HIDD));
                }
            }
            As[k4 * 4 + 0][r] = v.x;
            As[k4 * 4 + 1][r] = v.y;
            As[k4 * 4 + 2][r] = v.z;
            As[k4 * 4 + 3][r] = v.w;
        }
        // stage B: 512 float4 (fully coalesced)
#pragma unroll
        for (int i = 0; i < 2; i++) {
            int idx4 = t + 256 * i;
            int c4 = idx4 & 31, k = idx4 >> 5;
            int kk = k0 + k;
            const float* B = left ? (Wl + (size_t)kk * HIDD) : (Wr + (size_t)(kk - HIDD) * HIDD);
            *(float4*)&Bs[k][c4 * 4] = *(const float4*)(B + c4 * 4);
        }
        __syncthreads();
#pragma unroll
        for (int kk = 0; kk < 16; kk++) {
            float4 a0 = *(const float4*)&As[kk][ty * 8];
            float4 a1 = *(const float4*)&As[kk][ty * 8 + 4];
            float4 b0 = *(const float4*)&Bs[kk][tx * 8];
            float4 b1 = *(const float4*)&Bs[kk][tx * 8 + 4];
            float a[8] = {a0.x, a0.y, a0.z, a0.w, a1.x, a1.y, a1.z, a1.w};
            float b[8] = {b0.x, b0.y, b0.z, b0.w, b1.x, b1.y, b1.z, b1.w};
#pragma unroll
            for (int r = 0; r < 8; r++)
#pragma unroll
                for (int c = 0; c < 8; c++) acc[r][c] = fmaf(a[r], b[c], acc[r][c]);
        }
        __syncthreads();
    }
#pragma unroll
    for (int r = 0; r < 8; r++) {
        int row = row0 + ty * 8 + r;
        if (row >= nrows) break;
        float* o = out + (size_t)row * HIDD + tx * 8;
#pragma unroll
        for (int c = 0; c < 8; c++) {
            float v = acc[r][c] + bl[tx * 8 + c];
            o[c] = do_relu ? fmaxf(v, 0.f) : v;
        }
    }
}

// ---------------- launch ----------------
extern "C" void kernel_launch(void* const* d_in, const int* in_sizes, int n_in,
                              void* d_out, int out_size) {
    const float* x_pol    = (const float*)d_in[0];
    const int*   pol_sidx = (const int*)d_in[1];
    const float* x_comp   = (const float*)d_in[2];
    const int*   c_sidx   = (const int*)d_in[3];
    const int*   c_iidx   = (const int*)d_in[4];
    const int*   edge     = (const int*)d_in[5];
    const float* st_emb   = (const float*)d_in[6];
    const float* sec_emb  = (const float*)d_in[7];
    const float* ind_emb  = (const float*)d_in[8];
    const float* W_pol    = (const float*)d_in[9];
    const float* b_pol    = (const float*)d_in[10];
    const float* W_comp   = (const float*)d_in[11];
    const float* b_comp   = (const float*)d_in[12];
    const float* Wl1      = (const float*)d_in[13];
    const float* bl1      = (const float*)d_in[14];
    const float* Wr1      = (const float*)d_in[15];
    const float* Wl2      = (const float*)d_in[16];
    const float* bl2      = (const float*)d_in[17];
    const float* Wr2      = (const float*)d_in[18];
    float* out = (float*)d_out;

    const int E = in_sizes[5] / 2;
    const int* src = edge;
    const int* dst = edge + E;

    // one-time deterministic symbol-address lookup (query only; capture-safe)
    static float *p_h = nullptr, *p_h2, *p_accum, *p_cnt, *p_inv;
    if (p_h == nullptr) {
        cudaGetSymbolAddress((void**)&p_h, g_h);
        cudaGetSymbolAddress((void**)&p_h2, g_h2);
        cudaGetSymbolAddress((void**)&p_accum, g_accum);
        cudaGetSymbolAddress((void**)&p_cnt, g_cnt);
        cudaGetSymbolAddress((void**)&p_inv, g_inv);
    }

    const size_t accum_bytes = (size_t)NN * HIDD * sizeof(float);

    // degree counts (shared by both layers)
    cudaMemsetAsync(p_cnt, 0, NN * sizeof(float));
    count_kernel<<<(E + 255) / 256, 256>>>(dst, p_cnt, E);
    inv_kernel<<<(NN + 255) / 256, 256>>>(p_cnt, p_inv, NN);

    // encoders -> g_h
    encoder_kernel<<<(NP + 127) / 128, 256>>>(x_pol, 64, pol_sidx, st_emb, 8,
                                              (const int*)nullptr, (const float*)nullptr, 0,
                                              W_pol, b_pol, p_h, NP);
    encoder_kernel<<<(NC + 127) / 128, 256>>>(x_comp, 96, c_sidx, sec_emb, 8,
                                              c_iidx, ind_emb, 8,
                                              W_comp, b_comp, p_h + (size_t)NP * HIDD, NC);

    // ---- SAGE layer 1 ----
    cudaMemsetAsync(p_accum, 0, accum_bytes);
    {
        long long threads = (long long)E * 32;
        int blocks = (int)((threads + 255) / 256);
        scatter_kernel<<<blocks, 256>>>(p_h, p_accum, src, dst, E);
    }
    sage_gemm_kernel<<<(NN + 127) / 128, 256>>>(p_h, Wl1, bl1, Wr1, p_h2, NN, 1);

    // ---- SAGE layer 2 ----
    cudaMemsetAsync(p_accum, 0, accum_bytes);
    {
        long long threads = (long long)E * 32;
        int blocks = (int)((threads + 255) / 256);
        scatter_kernel<<<blocks, 256>>>(p_h2, p_accum, src, dst, E);
    }
    sage_gemm_kernel<<<(NN + 127) / 128, 256>>>(p_h2, Wl2, bl2, Wr2, out, NN, 0);
}

// round 4
// speedup vs baseline: 1.3755x; 1.3755x over previous
#include <cuda_runtime.h>
#include <cuda_bf16.h>
#include <cstdint>

#define NP 20000
#define NC 80000
#define NN 100000
#define HIDD 128

// ---------------- scratch (static device globals; no allocation) ----------------
__device__ float g_h[(size_t)NN * HIDD];      // layer input features
__device__ float g_h2[(size_t)NN * HIDD];     // layer-1 output
__device__ float g_accum[(size_t)NN * HIDD];  // scatter accumulator
__device__ float g_cnt[NN];
__device__ float g_inv[NN];

// ---------------- helpers ----------------
__device__ __forceinline__ void red_add_v4(float* p, float4 v) {
    asm volatile("red.global.add.v4.f32 [%0], {%1,%2,%3,%4};"
                 :: "l"(p), "f"(v.x), "f"(v.y), "f"(v.z), "f"(v.w) : "memory");
}

__device__ __forceinline__ uint32_t smem_u32(const void* p) {
    return (uint32_t)__cvta_generic_to_shared(p);
}

__device__ __forceinline__ void ldm_x4(uint32_t* r, uint32_t addr) {
    asm volatile("ldmatrix.sync.aligned.m8n8.x4.shared.b16 {%0,%1,%2,%3},[%4];"
                 : "=r"(r[0]), "=r"(r[1]), "=r"(r[2]), "=r"(r[3]) : "r"(addr));
}
__device__ __forceinline__ void ldm_x4_t(uint32_t* r, uint32_t addr) {
    asm volatile("ldmatrix.sync.aligned.m8n8.x4.trans.shared.b16 {%0,%1,%2,%3},[%4];"
                 : "=r"(r[0]), "=r"(r[1]), "=r"(r[2]), "=r"(r[3]) : "r"(addr));
}
__device__ __forceinline__ void mma_bf16(float* d, const uint32_t* a, const uint32_t* b) {
    asm volatile("mma.sync.aligned.m16n8k16.row.col.f32.bf16.bf16.f32 "
                 "{%0,%1,%2,%3},{%4,%5,%6,%7},{%8,%9},{%0,%1,%2,%3};"
                 : "+f"(d[0]), "+f"(d[1]), "+f"(d[2]), "+f"(d[3])
                 : "r"(a[0]), "r"(a[1]), "r"(a[2]), "r"(a[3]), "r"(b[0]), "r"(b[1]));
}

__device__ __forceinline__ void split2(float v, __nv_bfloat16& hi, __nv_bfloat16& lo) {
    hi = __float2bfloat16(v);
    lo = __float2bfloat16(v - __bfloat162float(hi));
}

// ---------------- degree count + reciprocal ----------------
__global__ void count_kernel(const int* __restrict__ dst, float* cnt, int E) {
    int e = blockIdx.x * blockDim.x + threadIdx.x;
    if (e < E) atomicAdd(&cnt[dst[e]], 1.0f);
}
__global__ void inv_kernel(const float* __restrict__ cnt, float* inv, int n) {
    int i = blockIdx.x * blockDim.x + threadIdx.x;
    if (i < n) inv[i] = 1.0f / fmaxf(cnt[i], 1.0f);
}

// ---------------- edge scatter: accum[dst] += h[src], warp per edge ----------------
__global__ void scatter_kernel(const float* __restrict__ h, float* __restrict__ accum,
                               const int* __restrict__ src, const int* __restrict__ dst,
                               int E) {
    int gtid = blockIdx.x * blockDim.x + threadIdx.x;
    int e = gtid >> 5;
    int lane = gtid & 31;
    if (e >= E) return;
    int s = 0, d = 0;
    if (lane == 0) { s = __ldg(&src[e]); d = __ldg(&dst[e]); }
    s = __shfl_sync(0xffffffffu, s, 0);
    d = __shfl_sync(0xffffffffu, d, 0);
    const float4 v = *(const float4*)(h + (size_t)s * HIDD + lane * 4);
    red_add_v4(accum + (size_t)d * HIDD + lane * 4, v);
}

// ================= split-bf16 tensor-core SAGE GEMM =================
// out[nrows,128] = act( [accum*inv | hin] @ [Wl;Wr] + bl )
// CTA: 128 rows x 128 cols, K=256, KT=32, 256 threads (8 warps, warp tile 32x64)
__global__ __launch_bounds__(256) void sage_mma_kernel(
    const float* __restrict__ hin,
    const float* __restrict__ Wl, const float* __restrict__ bl,
    const float* __restrict__ Wr,
    float* __restrict__ out, int nrows, int do_relu)
{
    __shared__ __align__(16) __nv_bfloat16 Ah[128][40];
    __shared__ __align__(16) __nv_bfloat16 Al[128][40];
    __shared__ __align__(16) __nv_bfloat16 Bh[32][136];
    __shared__ __align__(16) __nv_bfloat16 Bl[32][136];

    const int t = threadIdx.x;
    const int lane = t & 31;
    const int wid = t >> 5;
    const int warp_m = wid & 3;   // 0..3 -> 32 rows each
    const int warp_n = wid >> 2;  // 0..1 -> 64 cols each
    const int row0 = blockIdx.x * 128;

    float acc[2][8][4];
#pragma unroll
    for (int mt = 0; mt < 2; mt++)
#pragma unroll
        for (int nt = 0; nt < 8; nt++)
#pragma unroll
            for (int i = 0; i < 4; i++) acc[mt][nt][i] = 0.f;

    for (int k0 = 0; k0 < 256; k0 += 32) {
        const bool left = (k0 < 128);
        // stage A: 128 rows x 32 k = 1024 float4
#pragma unroll
        for (int i = 0; i < 4; i++) {
            int idx4 = t + 256 * i;
            int k4 = idx4 & 7, r = idx4 >> 3;
            int row = row0 + r;
            float4 v = make_float4(0.f, 0.f, 0.f, 0.f);
            if (row < nrows) {
                int kk = k0 + k4 * 4;
                if (left) {
                    v = *(const float4*)(g_accum + (size_t)row * HIDD + kk);
                    float iv = g_inv[row];
                    v.x *= iv; v.y *= iv; v.z *= iv; v.w *= iv;
                } else {
                    v = *(const float4*)(hin + (size_t)row * HIDD + (kk - 128));
                }
            }
            int c = k4 * 4;
            split2(v.x, Ah[r][c + 0], Al[r][c + 0]);
            split2(v.y, Ah[r][c + 1], Al[r][c + 1]);
            split2(v.z, Ah[r][c + 2], Al[r][c + 2]);
            split2(v.w, Ah[r][c + 3], Al[r][c + 3]);
        }
        // stage B: 32 k x 128 cols = 1024 float4
#pragma unroll
        for (int i = 0; i < 4; i++) {
            int idx4 = t + 256 * i;
            int c4 = idx4 & 31, kk = idx4 >> 5;
            int gk = k0 + kk;
            const float* B = left ? (Wl + (size_t)gk * HIDD) : (Wr + (size_t)(gk - 128) * HIDD);
            float4 v = *(const float4*)(B + c4 * 4);
            int c = c4 * 4;
            split2(v.x, Bh[kk][c + 0], Bl[kk][c + 0]);
            split2(v.y, Bh[kk][c + 1], Bl[kk][c + 1]);
            split2(v.z, Bh[kk][c + 2], Bl[kk][c + 2]);
            split2(v.w, Bh[kk][c + 3], Bl[kk][c + 3]);
        }
        __syncthreads();

#pragma unroll
        for (int ks = 0; ks < 32; ks += 16) {
            uint32_t aH[2][4], aL[2][4];
#pragma unroll
            for (int mt = 0; mt < 2; mt++) {
                int ar = warp_m * 32 + mt * 16 + (lane & 15);
                int ac = ks + (lane >> 4) * 8;
                ldm_x4(aH[mt], smem_u32(&Ah[ar][ac]));
                ldm_x4(aL[mt], smem_u32(&Al[ar][ac]));
            }
#pragma unroll
            for (int nt2 = 0; nt2 < 4; nt2++) {
                int br = ks + (lane & 15);
                int bc = warp_n * 64 + nt2 * 16 + (lane >> 4) * 8;
                uint32_t bH[4], bL[4];
                ldm_x4_t(bH, smem_u32(&Bh[br][bc]));
                ldm_x4_t(bL, smem_u32(&Bl[br][bc]));
#pragma unroll
                for (int mt = 0; mt < 2; mt++) {
                    mma_bf16(acc[mt][nt2 * 2 + 0], aH[mt], bH + 0);
                    mma_bf16(acc[mt][nt2 * 2 + 1], aH[mt], bH + 2);
                    mma_bf16(acc[mt][nt2 * 2 + 0], aH[mt], bL + 0);
                    mma_bf16(acc[mt][nt2 * 2 + 1], aH[mt], bL + 2);
                    mma_bf16(acc[mt][nt2 * 2 + 0], aL[mt], bH + 0);
                    mma_bf16(acc[mt][nt2 * 2 + 1], aL[mt], bH + 2);
                }
            }
        }
        __syncthreads();
    }

    // epilogue
    const int g = lane >> 2, tg = lane & 3;
#pragma unroll
    for (int mt = 0; mt < 2; mt++) {
#pragma unroll
        for (int nt = 0; nt < 8; nt++) {
            int col = warp_n * 64 + nt * 8 + tg * 2;
            float b0 = __ldg(&bl[col]), b1 = __ldg(&bl[col + 1]);
            int row = row0 + warp_m * 32 + mt * 16 + g;
            if (row < nrows) {
                float v0 = acc[mt][nt][0] + b0;
                float v1 = acc[mt][nt][1] + b1;
                if (do_relu) { v0 = fmaxf(v0, 0.f); v1 = fmaxf(v1, 0.f); }
                *(float2*)(out + (size_t)row * HIDD + col) = make_float2(v0, v1);
            }
            int row2 = row + 8;
            if (row2 < nrows) {
                float v0 = acc[mt][nt][2] + b0;
                float v1 = acc[mt][nt][3] + b1;
                if (do_relu) { v0 = fmaxf(v0, 0.f); v1 = fmaxf(v1, 0.f); }
                *(float2*)(out + (size_t)row2 * HIDD + col) = make_float2(v0, v1);
            }
        }
    }
}

// ================= split-bf16 tensor-core encoder =================
// out = relu(concat(x, emb1[i1], emb2[i2]) @ W + b); K runtime, Kpad mult of 16
__global__ __launch_bounds__(256) void encoder_mma_kernel(
    const float* __restrict__ xdyn, int xdim,
    const int* __restrict__ idx1, const float* __restrict__ emb1, int e1,
    const int* __restrict__ idx2, const float* __restrict__ emb2, int e2,
    const float* __restrict__ W, const float* __restrict__ bias,
    float* __restrict__ out, int nrows, int Kpad)
{
    __shared__ __align__(16) __nv_bfloat16 Ah[128][24];
    __shared__ __align__(16) __nv_bfloat16 Al[128][24];
    __shared__ __align__(16) __nv_bfloat16 Bh[16][136];
    __shared__ __align__(16) __nv_bfloat16 Bl[16][136];

    const int t = threadIdx.x;
    const int lane = t & 31;
    const int wid = t >> 5;
    const int warp_m = wid & 3;
    const int warp_n = wid >> 2;
    const int row0 = blockIdx.x * 128;
    const int K = xdim + e1 + e2;

    float acc[2][8][4];
#pragma unroll
    for (int mt = 0; mt < 2; mt++)
#pragma unroll
        for (int nt = 0; nt < 8; nt++)
#pragma unroll
            for (int i = 0; i < 4; i++) acc[mt][nt][i] = 0.f;

    for (int k0 = 0; k0 < Kpad; k0 += 16) {
        // stage A (gather/concat): 128 rows x 16 k = 2048 scalars -> 8/thread
#pragma unroll
        for (int i = 0; i < 8; i++) {
            int idx = t + 256 * i;
            int k = idx & 15, r = idx >> 4;
            int row = row0 + r;
            float v = 0.f;
            if (row < nrows) {
                int kk = k0 + k;
                if (kk < xdim) v = xdyn[(size_t)row * xdim + kk];
                else if (kk < xdim + e1) v = emb1[idx1[row] * e1 + (kk - xdim)];
                else if (kk < K) v = emb2[idx2[row] * e2 + (kk - xdim - e1)];
            }
            split2(v, Ah[r][k], Al[r][k]);
        }
        // stage B: 16 k x 128 cols = 512 float4 -> 2/thread
#pragma unroll
        for (int i = 0; i < 2; i++) {
            int idx4 = t + 256 * i;
            int c4 = idx4 & 31, kk = idx4 >> 5;
            int gk = k0 + kk;
            float4 v = make_float4(0.f, 0.f, 0.f, 0.f);
            if (gk < K) v = *(const float4*)(W + (size_t)gk * HIDD + c4 * 4);
            int c = c4 * 4;
            split2(v.x, Bh[kk][c + 0], Bl[kk][c + 0]);
            split2(v.y, Bh[kk][c + 1], Bl[kk][c + 1]);
            split2(v.z, Bh[kk][c + 2], Bl[kk][c + 2]);
            split2(v.w, Bh[kk][c + 3], Bl[kk][c + 3]);
        }
        __syncthreads();

        uint32_t aH[2][4], aL[2][4];
#pragma unroll
        for (int mt = 0; mt < 2; mt++) {
            int ar = warp_m * 32 + mt * 16 + (lane & 15);
            int ac = (lane >> 4) * 8;
            ldm_x4(aH[mt], smem_u32(&Ah[ar][ac]));
            ldm_x4(aL[mt], smem_u32(&Al[ar][ac]));
        }
#pragma unroll
        for (int nt2 = 0; nt2 < 4; nt2++) {
            int br = lane & 15;
            int bc = warp_n * 64 + nt2 * 16 + (lane >> 4) * 8;
            uint32_t bH[4], bL[4];
            ldm_x4_t(bH, smem_u32(&Bh[br][bc]));
            ldm_x4_t(bL, smem_u32(&Bl[br][bc]));
#pragma unroll
            for (int mt = 0; mt < 2; mt++) {
                mma_bf16(acc[mt][nt2 * 2 + 0], aH[mt], bH + 0);
                mma_bf16(acc[mt][nt2 * 2 + 1], aH[mt], bH + 2);
                mma_bf16(acc[mt][nt2 * 2 + 0], aH[mt], bL + 0);
                mma_bf16(acc[mt][nt2 * 2 + 1], aH[mt], bL + 2);
                mma_bf16(acc[mt][nt2 * 2 + 0], aL[mt], bH + 0);
                mma_bf16(acc[mt][nt2 * 2 + 1], aL[mt], bH + 2);
            }
        }
        __syncthreads();
    }

    const int g = lane >> 2, tg = lane & 3;
#pragma unroll
    for (int mt = 0; mt < 2; mt++) {
#pragma unroll
        for (int nt = 0; nt < 8; nt++) {
            int col = warp_n * 64 + nt * 8 + tg * 2;
            float b0 = __ldg(&bias[col]), b1 = __ldg(&bias[col + 1]);
            int row = row0 + warp_m * 32 + mt * 16 + g;
            if (row < nrows) {
                float v0 = fmaxf(acc[mt][nt][0] + b0, 0.f);
                float v1 = fmaxf(acc[mt][nt][1] + b1, 0.f);
                *(float2*)(out + (size_t)row * HIDD + col) = make_float2(v0, v1);
            }
            int row2 = row + 8;
            if (row2 < nrows) {
                float v0 = fmaxf(acc[mt][nt][2] + b0, 0.f);
                float v1 = fmaxf(acc[mt][nt][3] + b1, 0.f);
                *(float2*)(out + (size_t)row2 * HIDD + col) = make_float2(v0, v1);
            }
        }
    }
}

// ---------------- launch ----------------
extern "C" void kernel_launch(void* const* d_in, const int* in_sizes, int n_in,
                              void* d_out, int out_size) {
    const float* x_pol    = (const float*)d_in[0];
    const int*   pol_sidx = (const int*)d_in[1];
    const float* x_comp   = (const float*)d_in[2];
    const int*   c_sidx   = (const int*)d_in[3];
    const int*   c_iidx   = (const int*)d_in[4];
    const int*   edge     = (const int*)d_in[5];
    const float* st_emb   = (const float*)d_in[6];
    const float* sec_emb  = (const float*)d_in[7];
    const float* ind_emb  = (const float*)d_in[8];
    const float* W_pol    = (const float*)d_in[9];
    const float* b_pol    = (const float*)d_in[10];
    const float* W_comp   = (const float*)d_in[11];
    const float* b_comp   = (const float*)d_in[12];
    const float* Wl1      = (const float*)d_in[13];
    const float* bl1      = (const float*)d_in[14];
    const float* Wr1      = (const float*)d_in[15];
    const float* Wl2      = (const float*)d_in[16];
    const float* bl2      = (const float*)d_in[17];
    const float* Wr2      = (const float*)d_in[18];
    float* out = (float*)d_out;

    const int E = in_sizes[5] / 2;
    const int* src = edge;
    const int* dst = edge + E;

    static float *p_h = nullptr, *p_h2, *p_accum, *p_cnt, *p_inv;
    if (p_h == nullptr) {
        cudaGetSymbolAddress((void**)&p_h, g_h);
        cudaGetSymbolAddress((void**)&p_h2, g_h2);
        cudaGetSymbolAddress((void**)&p_accum, g_accum);
        cudaGetSymbolAddress((void**)&p_cnt, g_cnt);
        cudaGetSymbolAddress((void**)&p_inv, g_inv);
    }

    const size_t accum_bytes = (size_t)NN * HIDD * sizeof(float);

    // degree counts (shared by both layers)
    cudaMemsetAsync(p_cnt, 0, NN * sizeof(float));
    count_kernel<<<(E + 255) / 256, 256>>>(dst, p_cnt, E);
    inv_kernel<<<(NN + 255) / 256, 256>>>(p_cnt, p_inv, NN);

    // encoders -> g_h  (pol: K=72 -> pad 80; comp: K=112 already mult of 16)
    encoder_mma_kernel<<<(NP + 127) / 128, 256>>>(x_pol, 64, pol_sidx, st_emb, 8,
                                                  (const int*)nullptr, (const float*)nullptr, 0,
                                                  W_pol, b_pol, p_h, NP, 80);
    encoder_mma_kernel<<<(NC + 127) / 128, 256>>>(x_comp, 96, c_sidx, sec_emb, 8,
                                                  c_iidx, ind_emb, 8,
                                                  W_comp, b_comp, p_h + (size_t)NP * HIDD, NC, 112);

    // ---- SAGE layer 1 ----
    cudaMemsetAsync(p_accum, 0, accum_bytes);
    {
        long long threads = (long long)E * 32;
        int blocks = (int)((threads + 255) / 256);
        scatter_kernel<<<blocks, 256>>>(p_h, p_accum, src, dst, E);
    }
    sage_mma_kernel<<<(NN + 127) / 128, 256>>>(p_h, Wl1, bl1, Wr1, p_h2, NN, 1);

    // ---- SAGE layer 2 ----
    cudaMemsetAsync(p_accum, 0, accum_bytes);
    {
        long long threads = (long long)E * 32;
        int blocks = (int)((threads + 255) / 256);
        scatter_kernel<<<blocks, 256>>>(p_h2, p_accum, src, dst, E);
    }
    sage_mma_kernel<<<(NN + 127) / 128, 256>>>(p_h2, Wl2, bl2, Wr2, out, NN, 0);
}

// round 5
// speedup vs baseline: 1.6260x; 1.1821x over previous
#include <cuda_runtime.h>
#include <cuda_bf16.h>
#include <cstdint>

#define NP 20000
#define NC 80000
#define NN 100000
#define HIDD 128

// ---------------- scratch (static device globals; no allocation) ----------------
__device__ float g_h[(size_t)NN * HIDD];      // layer input features
__device__ float g_h2[(size_t)NN * HIDD];     // layer-1 output
__device__ float g_accum[(size_t)NN * HIDD];  // scatter accumulator
__device__ float g_cnt[NN];
__device__ float g_inv[NN];
__device__ float g_sproj[50 * HIDD];          // state_emb @ W_pol[64:72] + b_pol
__device__ float g_secproj[12 * HIDD];        // sector_emb @ W_comp[96:104] + b_comp
__device__ float g_iproj[150 * HIDD];         // ind_emb @ W_comp[104:112]

// ---------------- helpers ----------------
__device__ __forceinline__ void red_add_v4(float* p, float4 v) {
    asm volatile("red.global.add.v4.f32 [%0], {%1,%2,%3,%4};"
                 :: "l"(p), "f"(v.x), "f"(v.y), "f"(v.z), "f"(v.w) : "memory");
}
__device__ __forceinline__ uint32_t smem_u32(const void* p) {
    return (uint32_t)__cvta_generic_to_shared(p);
}
__device__ __forceinline__ void ldm_x4(uint32_t* r, uint32_t addr) {
    asm volatile("ldmatrix.sync.aligned.m8n8.x4.shared.b16 {%0,%1,%2,%3},[%4];"
                 : "=r"(r[0]), "=r"(r[1]), "=r"(r[2]), "=r"(r[3]) : "r"(addr));
}
__device__ __forceinline__ void ldm_x4_t(uint32_t* r, uint32_t addr) {
    asm volatile("ldmatrix.sync.aligned.m8n8.x4.trans.shared.b16 {%0,%1,%2,%3},[%4];"
                 : "=r"(r[0]), "=r"(r[1]), "=r"(r[2]), "=r"(r[3]) : "r"(addr));
}
__device__ __forceinline__ void mma_bf16(float* d, const uint32_t* a, const uint32_t* b) {
    asm volatile("mma.sync.aligned.m16n8k16.row.col.f32.bf16.bf16.f32 "
                 "{%0,%1,%2,%3},{%4,%5,%6,%7},{%8,%9},{%0,%1,%2,%3};"
                 : "+f"(d[0]), "+f"(d[1]), "+f"(d[2]), "+f"(d[3])
                 : "r"(a[0]), "r"(a[1]), "r"(a[2]), "r"(a[3]), "r"(b[0]), "r"(b[1]));
}
__device__ __forceinline__ void split2(float v, __nv_bfloat16& hi, __nv_bfloat16& lo) {
    hi = __float2bfloat16(v);
    lo = __float2bfloat16(v - __bfloat162float(hi));
}

// ---------------- degree count + reciprocal ----------------
__global__ void count_kernel(const int* __restrict__ dst, float* cnt, int E) {
    int e = blockIdx.x * blockDim.x + threadIdx.x;
    if (e < E) atomicAdd(&cnt[dst[e]], 1.0f);
}
__global__ void inv_kernel(const float* __restrict__ cnt, float* inv, int n) {
    int i = blockIdx.x * blockDim.x + threadIdx.x;
    if (i < n) inv[i] = 1.0f / fmaxf(cnt[i], 1.0f);
}

// ---------------- embedding projection tables ----------------
// 27136 output elements: [0,6400) state, [6400,7936) sector, [7936,27136) industry
__global__ void embproj_kernel(const float* __restrict__ st_emb,
                               const float* __restrict__ sec_emb,
                               const float* __restrict__ ind_emb,
                               const float* __restrict__ W_pol,  // [72,128]
                               const float* __restrict__ b_pol,
                               const float* __restrict__ W_comp, // [112,128]
                               const float* __restrict__ b_comp,
                               float* __restrict__ sproj, float* __restrict__ secproj,
                               float* __restrict__ iproj) {
    int i = blockIdx.x * blockDim.x + threadIdx.x;
    if (i >= 27136) return;
    const float* emb; const float* W; const float* bias; float* outp; int r, c;
    if (i < 6400) {
        r = i >> 7; c = i & 127;
        emb = st_emb + r * 8; W = W_pol + 64 * HIDD; bias = b_pol; outp = sproj + i;
    } else if (i < 7936) {
        int j = i - 6400; r = j >> 7; c = j & 127;
        emb = sec_emb + r * 8; W = W_comp + 96 * HIDD; bias = b_comp; outp = secproj + j;
    } else {
        int j = i - 7936; r = j >> 7; c = j & 127;
        emb = ind_emb + r * 8; W = W_comp + 104 * HIDD; bias = nullptr; outp = iproj + j;
    }
    float s = bias ? bias[c] : 0.f;
#pragma unroll
    for (int j = 0; j < 8; j++) s = fmaf(emb[j], W[j * HIDD + c], s);
    *outp = s;
}

// ---------------- edge scatter: accum[dst] += h[src], warp per edge ----------------
__global__ void scatter_kernel(const float* __restrict__ h, float* __restrict__ accum,
                               const int* __restrict__ src, const int* __restrict__ dst,
                               int E) {
    int gtid = blockIdx.x * blockDim.x + threadIdx.x;
    int e = gtid >> 5;
    int lane = gtid & 31;
    if (e >= E) return;
    int s = 0, d = 0;
    if (lane == 0) { s = __ldg(&src[e]); d = __ldg(&dst[e]); }
    s = __shfl_sync(0xffffffffu, s, 0);
    d = __shfl_sync(0xffffffffu, d, 0);
    const float4 v = *(const float4*)(h + (size_t)s * HIDD + lane * 4);
    red_add_v4(accum + (size_t)d * HIDD + lane * 4, v);
}

// ================= split-bf16 tensor-core SAGE GEMM =================
// out[nrows,128] = act( [accum*inv | hin] @ [Wl;Wr] + bl )
__global__ __launch_bounds__(256, 2) void sage_mma_kernel(
    const float* __restrict__ hin,
    const float* __restrict__ Wl, const float* __restrict__ bl,
    const float* __restrict__ Wr,
    float* __restrict__ out, int nrows, int do_relu)
{
    __shared__ __align__(16) __nv_bfloat16 Ah[128][40];
    __shared__ __align__(16) __nv_bfloat16 Al[128][40];
    __shared__ __align__(16) __nv_bfloat16 Bh[32][136];
    __shared__ __align__(16) __nv_bfloat16 Bl[32][136];

    const int t = threadIdx.x;
    const int lane = t & 31;
    const int wid = t >> 5;
    const int warp_m = wid & 3;
    const int warp_n = wid >> 2;
    const int row0 = blockIdx.x * 128;

    float acc[2][8][4];
#pragma unroll
    for (int mt = 0; mt < 2; mt++)
#pragma unroll
        for (int nt = 0; nt < 8; nt++)
#pragma unroll
            for (int i = 0; i < 4; i++) acc[mt][nt][i] = 0.f;

    for (int k0 = 0; k0 < 256; k0 += 32) {
        const bool left = (k0 < 128);
#pragma unroll
        for (int i = 0; i < 4; i++) {
            int idx4 = t + 256 * i;
            int k4 = idx4 & 7, r = idx4 >> 3;
            int row = row0 + r;
            float4 v = make_float4(0.f, 0.f, 0.f, 0.f);
            if (row < nrows) {
                int kk = k0 + k4 * 4;
                if (left) {
                    v = *(const float4*)(g_accum + (size_t)row * HIDD + kk);
                    float iv = g_inv[row];
                    v.x *= iv; v.y *= iv; v.z *= iv; v.w *= iv;
                } else {
                    v = *(const float4*)(hin + (size_t)row * HIDD + (kk - 128));
                }
            }
            int c = k4 * 4;
            split2(v.x, Ah[r][c + 0], Al[r][c + 0]);
            split2(v.y, Ah[r][c + 1], Al[r][c + 1]);
            split2(v.z, Ah[r][c + 2], Al[r][c + 2]);
            split2(v.w, Ah[r][c + 3], Al[r][c + 3]);
        }
#pragma unroll
        for (int i = 0; i < 4; i++) {
            int idx4 = t + 256 * i;
            int c4 = idx4 & 31, kk = idx4 >> 5;
            int gk = k0 + kk;
            const float* B = left ? (Wl + (size_t)gk * HIDD) : (Wr + (size_t)(gk - 128) * HIDD);
            float4 v = *(const float4*)(B + c4 * 4);
            int c = c4 * 4;
            split2(v.x, Bh[kk][c + 0], Bl[kk][c + 0]);
            split2(v.y, Bh[kk][c + 1], Bl[kk][c + 1]);
            split2(v.z, Bh[kk][c + 2], Bl[kk][c + 2]);
            split2(v.w, Bh[kk][c + 3], Bl[kk][c + 3]);
        }
        __syncthreads();

#pragma unroll
        for (int ks = 0; ks < 32; ks += 16) {
            uint32_t aH[2][4], aL[2][4];
#pragma unroll
            for (int mt = 0; mt < 2; mt++) {
                int ar = warp_m * 32 + mt * 16 + (lane & 15);
                int ac = ks + (lane >> 4) * 8;
                ldm_x4(aH[mt], smem_u32(&Ah[ar][ac]));
                ldm_x4(aL[mt], smem_u32(&Al[ar][ac]));
            }
#pragma unroll
            for (int nt2 = 0; nt2 < 4; nt2++) {
                int br = ks + (lane & 15);
                int bc = warp_n * 64 + nt2 * 16 + (lane >> 4) * 8;
                uint32_t bH[4], bL[4];
                ldm_x4_t(bH, smem_u32(&Bh[br][bc]));
                ldm_x4_t(bL, smem_u32(&Bl[br][bc]));
#pragma unroll
                for (int mt = 0; mt < 2; mt++) {
                    mma_bf16(acc[mt][nt2 * 2 + 0], aH[mt], bH + 0);
                    mma_bf16(acc[mt][nt2 * 2 + 1], aH[mt], bH + 2);
                    mma_bf16(acc[mt][nt2 * 2 + 0], aH[mt], bL + 0);
                    mma_bf16(acc[mt][nt2 * 2 + 1], aH[mt], bL + 2);
                    mma_bf16(acc[mt][nt2 * 2 + 0], aL[mt], bH + 0);
                    mma_bf16(acc[mt][nt2 * 2 + 1], aL[mt], bH + 2);
                }
            }
        }
        __syncthreads();
    }

    const int g = lane >> 2, tg = lane & 3;
#pragma unroll
    for (int mt = 0; mt < 2; mt++) {
#pragma unroll
        for (int nt = 0; nt < 8; nt++) {
            int col = warp_n * 64 + nt * 8 + tg * 2;
            float b0 = __ldg(&bl[col]), b1 = __ldg(&bl[col + 1]);
            int row = row0 + warp_m * 32 + mt * 16 + g;
            if (row < nrows) {
                float v0 = acc[mt][nt][0] + b0;
                float v1 = acc[mt][nt][1] + b1;
                if (do_relu) { v0 = fmaxf(v0, 0.f); v1 = fmaxf(v1, 0.f); }
                *(float2*)(out + (size_t)row * HIDD + col) = make_float2(v0, v1);
            }
            int row2 = row + 8;
            if (row2 < nrows) {
                float v0 = acc[mt][nt][2] + b0;
                float v1 = acc[mt][nt][3] + b1;
                if (do_relu) { v0 = fmaxf(v0, 0.f); v1 = fmaxf(v1, 0.f); }
                *(float2*)(out + (size_t)row2 * HIDD + col) = make_float2(v0, v1);
            }
        }
    }
}

// ================= encoder: out = relu(x @ Wx + proj1[i1] + proj2[i2]) =================
// Kx is 64 or 96 (multiple of 32). Clean coalesced staging, no gather.
__global__ __launch_bounds__(256, 2) void encoder2_kernel(
    const float* __restrict__ x, int Kx,
    const int* __restrict__ idx1, const float* __restrict__ proj1,
    const int* __restrict__ idx2, const float* __restrict__ proj2,
    const float* __restrict__ W,  // [K,128] row-major, first Kx rows used
    float* __restrict__ out, int nrows)
{
    __shared__ __align__(16) __nv_bfloat16 Ah[128][40];
    __shared__ __align__(16) __nv_bfloat16 Al[128][40];
    __shared__ __align__(16) __nv_bfloat16 Bh[32][136];
    __shared__ __align__(16) __nv_bfloat16 Bl[32][136];

    const int t = threadIdx.x;
    const int lane = t & 31;
    const int wid = t >> 5;
    const int warp_m = wid & 3;
    const int warp_n = wid >> 2;
    const int row0 = blockIdx.x * 128;

    float acc[2][8][4];
#pragma unroll
    for (int mt = 0; mt < 2; mt++)
#pragma unroll
        for (int nt = 0; nt < 8; nt++)
#pragma unroll
            for (int i = 0; i < 4; i++) acc[mt][nt][i] = 0.f;

    for (int k0 = 0; k0 < Kx; k0 += 32) {
#pragma unroll
        for (int i = 0; i < 4; i++) {
            int idx4 = t + 256 * i;
            int k4 = idx4 & 7, r = idx4 >> 3;
            int row = row0 + r;
            float4 v = make_float4(0.f, 0.f, 0.f, 0.f);
            if (row < nrows) v = *(const float4*)(x + (size_t)row * Kx + k0 + k4 * 4);
            int c = k4 * 4;
            split2(v.x, Ah[r][c + 0], Al[r][c + 0]);
            split2(v.y, Ah[r][c + 1], Al[r][c + 1]);
            split2(v.z, Ah[r][c + 2], Al[r][c + 2]);
            split2(v.w, Ah[r][c + 3], Al[r][c + 3]);
        }
#pragma unroll
        for (int i = 0; i < 4; i++) {
            int idx4 = t + 256 * i;
            int c4 = idx4 & 31, kk = idx4 >> 5;
            float4 v = *(const float4*)(W + (size_t)(k0 + kk) * HIDD + c4 * 4);
            int c = c4 * 4;
            split2(v.x, Bh[kk][c + 0], Bl[kk][c + 0]);
            split2(v.y, Bh[kk][c + 1], Bl[kk][c + 1]);
            split2(v.z, Bh[kk][c + 2], Bl[kk][c + 2]);
            split2(v.w, Bh[kk][c + 3], Bl[kk][c + 3]);
        }
        __syncthreads();

#pragma unroll
        for (int ks = 0; ks < 32; ks += 16) {
            uint32_t aH[2][4], aL[2][4];
#pragma unroll
            for (int mt = 0; mt < 2; mt++) {
                int ar = warp_m * 32 + mt * 16 + (lane & 15);
                int ac = ks + (lane >> 4) * 8;
                ldm_x4(aH[mt], smem_u32(&Ah[ar][ac]));
                ldm_x4(aL[mt], smem_u32(&Al[ar][ac]));
            }
#pragma unroll
            for (int nt2 = 0; nt2 < 4; nt2++) {
                int br = ks + (lane & 15);
                int bc = warp_n * 64 + nt2 * 16 + (lane >> 4) * 8;
                uint32_t bH[4], bL[4];
                ldm_x4_t(bH, smem_u32(&Bh[br][bc]));
                ldm_x4_t(bL, smem_u32(&Bl[br][bc]));
#pragma unroll
                for (int mt = 0; mt < 2; mt++) {
                    mma_bf16(acc[mt][nt2 * 2 + 0], aH[mt], bH + 0);
                    mma_bf16(acc[mt][nt2 * 2 + 1], aH[mt], bH + 2);
                    mma_bf16(acc[mt][nt2 * 2 + 0], aH[mt], bL + 0);
                    mma_bf16(acc[mt][nt2 * 2 + 1], aH[mt], bL + 2);
                    mma_bf16(acc[mt][nt2 * 2 + 0], aL[mt], bH + 0);
                    mma_bf16(acc[mt][nt2 * 2 + 1], aL[mt], bH + 2);
                }
            }
        }
        __syncthreads();
    }

    const int g = lane >> 2, tg = lane & 3;
#pragma unroll
    for (int mt = 0; mt < 2; mt++) {
#pragma unroll
        for (int nt = 0; nt < 8; nt++) {
            int col = warp_n * 64 + nt * 8 + tg * 2;
            int row = row0 + warp_m * 32 + mt * 16 + g;
            if (row < nrows) {
                const float* p1 = proj1 + (size_t)idx1[row] * HIDD;
                float a0 = p1[col], a1 = p1[col + 1];
                if (idx2) {
                    const float* p2 = proj2 + (size_t)idx2[row] * HIDD;
                    a0 += p2[col]; a1 += p2[col + 1];
                }
                float v0 = fmaxf(acc[mt][nt][0] + a0, 0.f);
                float v1 = fmaxf(acc[mt][nt][1] + a1, 0.f);
                *(float2*)(out + (size_t)row * HIDD + col) = make_float2(v0, v1);
            }
            int row2 = row + 8;
            if (row2 < nrows) {
                const float* p1 = proj1 + (size_t)idx1[row2] * HIDD;
                float a0 = p1[col], a1 = p1[col + 1];
                if (idx2) {
                    const float* p2 = proj2 + (size_t)idx2[row2] * HIDD;
                    a0 += p2[col]; a1 += p2[col + 1];
                }
                float v0 = fmaxf(acc[mt][nt][2] + a0, 0.f);
                float v1 = fmaxf(acc[mt][nt][3] + a1, 0.f);
                *(float2*)(out + (size_t)row2 * HIDD + col) = make_float2(v0, v1);
            }
        }
    }
}

// ---------------- launch ----------------
extern "C" void kernel_launch(void* const* d_in, const int* in_sizes, int n_in,
                              void* d_out, int out_size) {
    const float* x_pol    = (const float*)d_in[0];
    const int*   pol_sidx = (const int*)d_in[1];
    const float* x_comp   = (const float*)d_in[2];
    const int*   c_sidx   = (const int*)d_in[3];
    const int*   c_iidx   = (const int*)d_in[4];
    const int*   edge     = (const int*)d_in[5];
    const float* st_emb   = (const float*)d_in[6];
    const float* sec_emb  = (const float*)d_in[7];
    const float* ind_emb  = (const float*)d_in[8];
    const float* W_pol    = (const float*)d_in[9];
    const float* b_pol    = (const float*)d_in[10];
    const float* W_comp   = (const float*)d_in[11];
    const float* b_comp   = (const float*)d_in[12];
    const float* Wl1      = (const float*)d_in[13];
    const float* bl1      = (const float*)d_in[14];
    const float* Wr1      = (const float*)d_in[15];
    const float* Wl2      = (const float*)d_in[16];
    const float* bl2      = (const float*)d_in[17];
    const float* Wr2      = (const float*)d_in[18];
    float* out = (float*)d_out;

    const int E = in_sizes[5] / 2;
    const int* src = edge;
    const int* dst = edge + E;

    static float *p_h = nullptr, *p_h2, *p_accum, *p_cnt, *p_inv, *p_sp, *p_secp, *p_ip;
    if (p_h == nullptr) {
        cudaGetSymbolAddress((void**)&p_h, g_h);
        cudaGetSymbolAddress((void**)&p_h2, g_h2);
        cudaGetSymbolAddress((void**)&p_accum, g_accum);
        cudaGetSymbolAddress((void**)&p_cnt, g_cnt);
        cudaGetSymbolAddress((void**)&p_inv, g_inv);
        cudaGetSymbolAddress((void**)&p_sp, g_sproj);
        cudaGetSymbolAddress((void**)&p_secp, g_secproj);
        cudaGetSymbolAddress((void**)&p_ip, g_iproj);
    }

    const size_t accum_bytes = (size_t)NN * HIDD * sizeof(float);

    // degree counts + embedding projections
    cudaMemsetAsync(p_cnt, 0, NN * sizeof(float));
    count_kernel<<<(E + 255) / 256, 256>>>(dst, p_cnt, E);
    inv_kernel<<<(NN + 255) / 256, 256>>>(p_cnt, p_inv, NN);
    embproj_kernel<<<(27136 + 255) / 256, 256>>>(st_emb, sec_emb, ind_emb,
                                                 W_pol, b_pol, W_comp, b_comp,
                                                 p_sp, p_secp, p_ip);

    // encoders -> g_h
    encoder2_kernel<<<(NP + 127) / 128, 256>>>(x_pol, 64, pol_sidx, p_sp,
                                               (const int*)nullptr, (const float*)nullptr,
                                               W_pol, p_h, NP);
    encoder2_kernel<<<(NC + 127) / 128, 256>>>(x_comp, 96, c_sidx, p_secp,
                                               c_iidx, p_ip,
                                               W_comp, p_h + (size_t)NP * HIDD, NC);

    // ---- SAGE layer 1 ----
    cudaMemsetAsync(p_accum, 0, accum_bytes);
    {
        long long threads = (long long)E * 32;
        int blocks = (int)((threads + 255) / 256);
        scatter_kernel<<<blocks, 256>>>(p_h, p_accum, src, dst, E);
    }
    sage_mma_kernel<<<(NN + 127) / 128, 256>>>(p_h, Wl1, bl1, Wr1, p_h2, NN, 1);

    // ---- SAGE layer 2 ----
    cudaMemsetAsync(p_accum, 0, accum_bytes);
    {
        long long threads = (long long)E * 32;
        int blocks = (int)((threads + 255) / 256);
        scatter_kernel<<<blocks, 256>>>(p_h2, p_accum, src, dst, E);
    }
    sage_mma_kernel<<<(NN + 127) / 128, 256>>>(p_h2, Wl2, bl2, Wr2, out, NN, 0);
}

// round 6
// speedup vs baseline: 2.8376x; 1.7451x over previous
#include <cuda_runtime.h>
#include <cuda_bf16.h>
#include <cstdint>

#define NP 20000
#define NC 80000
#define NN 100000
#define HIDD 128
#define EMAX 1600000

// ---------------- scratch (static device globals; no allocation) ----------------
__device__ float g_h[(size_t)NN * HIDD];      // layer input features
__device__ float g_h2[(size_t)NN * HIDD];     // layer-1 output
__device__ float g_mean[(size_t)NN * HIDD];   // aggregated mean per node
__device__ int   g_cnt_i[NN];                 // in-degree
__device__ int   g_row[NN];                   // CSR row starts
__device__ int   g_cur[NN];                   // fill cursors
__device__ int   g_csr[EMAX];                 // CSR src ids
__device__ int   g_blk[512];                  // block sums for scan
__device__ float g_sproj[50 * HIDD];
__device__ float g_secproj[12 * HIDD];
__device__ float g_iproj[150 * HIDD];

// ---------------- helpers ----------------
__device__ __forceinline__ uint32_t smem_u32(const void* p) {
    return (uint32_t)__cvta_generic_to_shared(p);
}
__device__ __forceinline__ void ldm_x4(uint32_t* r, uint32_t addr) {
    asm volatile("ldmatrix.sync.aligned.m8n8.x4.shared.b16 {%0,%1,%2,%3},[%4];"
                 : "=r"(r[0]), "=r"(r[1]), "=r"(r[2]), "=r"(r[3]) : "r"(addr));
}
__device__ __forceinline__ void ldm_x4_t(uint32_t* r, uint32_t addr) {
    asm volatile("ldmatrix.sync.aligned.m8n8.x4.trans.shared.b16 {%0,%1,%2,%3},[%4];"
                 : "=r"(r[0]), "=r"(r[1]), "=r"(r[2]), "=r"(r[3]) : "r"(addr));
}
__device__ __forceinline__ void mma_bf16(float* d, const uint32_t* a, const uint32_t* b) {
    asm volatile("mma.sync.aligned.m16n8k16.row.col.f32.bf16.bf16.f32 "
                 "{%0,%1,%2,%3},{%4,%5,%6,%7},{%8,%9},{%0,%1,%2,%3};"
                 : "+f"(d[0]), "+f"(d[1]), "+f"(d[2]), "+f"(d[3])
                 : "r"(a[0]), "r"(a[1]), "r"(a[2]), "r"(a[3]), "r"(b[0]), "r"(b[1]));
}
__device__ __forceinline__ void split2(float v, __nv_bfloat16& hi, __nv_bfloat16& lo) {
    hi = __float2bfloat16(v);
    lo = __float2bfloat16(v - __bfloat162float(hi));
}

// ---------------- CSR build ----------------
__global__ void count_int_kernel(const int* __restrict__ dst, int* cnt, int E) {
    int e = blockIdx.x * blockDim.x + threadIdx.x;
    if (e < E) atomicAdd(&cnt[dst[e]], 1);
}
__global__ void blk_reduce_kernel(const int* __restrict__ cnt, int* blk, int n) {
    __shared__ int s[256];
    int idx = blockIdx.x * 256 + threadIdx.x;
    s[threadIdx.x] = (idx < n) ? cnt[idx] : 0;
    __syncthreads();
    for (int off = 128; off > 0; off >>= 1) {
        if (threadIdx.x < off) s[threadIdx.x] += s[threadIdx.x + off];
        __syncthreads();
    }
    if (threadIdx.x == 0) blk[blockIdx.x] = s[0];
}
__global__ void scan_blk_kernel(int* blk, int nb) {
    if (threadIdx.x == 0 && blockIdx.x == 0) {
        int run = 0;
        for (int b = 0; b < nb; b++) { int t = blk[b]; blk[b] = run; run += t; }
    }
}
__global__ void blk_scan_write_kernel(const int* __restrict__ cnt, const int* __restrict__ blk,
                                      int* row, int* cur, int n) {
    __shared__ int s[256];
    int t = threadIdx.x;
    int idx = blockIdx.x * 256 + t;
    int v = (idx < n) ? cnt[idx] : 0;
    s[t] = v;
    __syncthreads();
#pragma unroll
    for (int off = 1; off < 256; off <<= 1) {
        int x = (t >= off) ? s[t - off] : 0;
        __syncthreads();
        s[t] += x;
        __syncthreads();
    }
    if (idx < n) {
        int excl = s[t] - v + blk[blockIdx.x];
        row[idx] = excl;
        cur[idx] = excl;
    }
}
__global__ void fill_csr_kernel(const int* __restrict__ src, const int* __restrict__ dst,
                                int* cur, int* csr, int E) {
    int e = blockIdx.x * blockDim.x + threadIdx.x;
    if (e < E) {
        int slot = atomicAdd(&cur[dst[e]], 1);
        csr[slot] = src[e];
    }
}

// ---------------- warp-per-node gather + mean ----------------
__global__ __launch_bounds__(256) void gather_mean_kernel(const float* __restrict__ h,
                                                          float* __restrict__ mout) {
    int w = (blockIdx.x * blockDim.x + threadIdx.x) >> 5;
    int lane = threadIdx.x & 31;
    if (w >= NN) return;
    int beg = g_row[w];
    int n = g_cnt_i[w];
    float ax = 0.f, ay = 0.f, az = 0.f, aw = 0.f;
    int i = 0;
    for (; i + 4 <= n; i += 4) {
        int s0 = __ldg(&g_csr[beg + i + 0]);
        int s1 = __ldg(&g_csr[beg + i + 1]);
        int s2 = __ldg(&g_csr[beg + i + 2]);
        int s3 = __ldg(&g_csr[beg + i + 3]);
        float4 v0 = *(const float4*)(h + (size_t)s0 * HIDD + lane * 4);
        float4 v1 = *(const float4*)(h + (size_t)s1 * HIDD + lane * 4);
        float4 v2 = *(const float4*)(h + (size_t)s2 * HIDD + lane * 4);
        float4 v3 = *(const float4*)(h + (size_t)s3 * HIDD + lane * 4);
        ax += v0.x + v1.x + v2.x + v3.x;
        ay += v0.y + v1.y + v2.y + v3.y;
        az += v0.z + v1.z + v2.z + v3.z;
        aw += v0.w + v1.w + v2.w + v3.w;
    }
    for (; i < n; i++) {
        int s0 = __ldg(&g_csr[beg + i]);
        float4 v0 = *(const float4*)(h + (size_t)s0 * HIDD + lane * 4);
        ax += v0.x; ay += v0.y; az += v0.z; aw += v0.w;
    }
    float inv = 1.f / fmaxf((float)n, 1.f);
    float4 r = make_float4(ax * inv, ay * inv, az * inv, aw * inv);
    *(float4*)(mout + (size_t)w * HIDD + lane * 4) = r;
}

// ---------------- embedding projection tables ----------------
__global__ void embproj_kernel(const float* __restrict__ st_emb,
                               const float* __restrict__ sec_emb,
                               const float* __restrict__ ind_emb,
                               const float* __restrict__ W_pol,
                               const float* __restrict__ b_pol,
                               const float* __restrict__ W_comp,
                               const float* __restrict__ b_comp,
                               float* __restrict__ sproj, float* __restrict__ secproj,
                               float* __restrict__ iproj) {
    int i = blockIdx.x * blockDim.x + threadIdx.x;
    if (i >= 27136) return;
    const float* emb; const float* W; const float* bias; float* outp; int r, c;
    if (i < 6400) {
        r = i >> 7; c = i & 127;
        emb = st_emb + r * 8; W = W_pol + 64 * HIDD; bias = b_pol; outp = sproj + i;
    } else if (i < 7936) {
        int j = i - 6400; r = j >> 7; c = j & 127;
        emb = sec_emb + r * 8; W = W_comp + 96 * HIDD; bias = b_comp; outp = secproj + j;
    } else {
        int j = i - 7936; r = j >> 7; c = j & 127;
        emb = ind_emb + r * 8; W = W_comp + 104 * HIDD; bias = nullptr; outp = iproj + j;
    }
    float s = bias ? bias[c] : 0.f;
#pragma unroll
    for (int j = 0; j < 8; j++) s = fmaf(emb[j], W[j * HIDD + c], s);
    *outp = s;
}

// ================= split-bf16 tensor-core SAGE GEMM =================
// out[nrows,128] = act( [g_mean | hin] @ [Wl;Wr] + bl )
__global__ __launch_bounds__(256, 2) void sage_mma_kernel(
    const float* __restrict__ hin,
    const float* __restrict__ Wl, const float* __restrict__ bl,
    const float* __restrict__ Wr,
    float* __restrict__ out, int nrows, int do_relu)
{
    __shared__ __align__(16) __nv_bfloat16 Ah[128][40];
    __shared__ __align__(16) __nv_bfloat16 Al[128][40];
    __shared__ __align__(16) __nv_bfloat16 Bh[32][136];
    __shared__ __align__(16) __nv_bfloat16 Bl[32][136];

    const int t = threadIdx.x;
    const int lane = t & 31;
    const int wid = t >> 5;
    const int warp_m = wid & 3;
    const int warp_n = wid >> 2;
    const int row0 = blockIdx.x * 128;

    float acc[2][8][4];
#pragma unroll
    for (int mt = 0; mt < 2; mt++)
#pragma unroll
        for (int nt = 0; nt < 8; nt++)
#pragma unroll
            for (int i = 0; i < 4; i++) acc[mt][nt][i] = 0.f;

    for (int k0 = 0; k0 < 256; k0 += 32) {
        const bool left = (k0 < 128);
#pragma unroll
        for (int i = 0; i < 4; i++) {
            int idx4 = t + 256 * i;
            int k4 = idx4 & 7, r = idx4 >> 3;
            int row = row0 + r;
            float4 v = make_float4(0.f, 0.f, 0.f, 0.f);
            if (row < nrows) {
                int kk = k0 + k4 * 4;
                if (left) v = *(const float4*)(g_mean + (size_t)row * HIDD + kk);
                else      v = *(const float4*)(hin + (size_t)row * HIDD + (kk - 128));
            }
            int c = k4 * 4;
            split2(v.x, Ah[r][c + 0], Al[r][c + 0]);
            split2(v.y, Ah[r][c + 1], Al[r][c + 1]);
            split2(v.z, Ah[r][c + 2], Al[r][c + 2]);
            split2(v.w, Ah[r][c + 3], Al[r][c + 3]);
        }
#pragma unroll
        for (int i = 0; i < 4; i++) {
            int idx4 = t + 256 * i;
            int c4 = idx4 & 31, kk = idx4 >> 5;
            int gk = k0 + kk;
            const float* B = left ? (Wl + (size_t)gk * HIDD) : (Wr + (size_t)(gk - 128) * HIDD);
            float4 v = *(const float4*)(B + c4 * 4);
            int c = c4 * 4;
            split2(v.x, Bh[kk][c + 0], Bl[kk][c + 0]);
            split2(v.y, Bh[kk][c + 1], Bl[kk][c + 1]);
            split2(v.z, Bh[kk][c + 2], Bl[kk][c + 2]);
            split2(v.w, Bh[kk][c + 3], Bl[kk][c + 3]);
        }
        __syncthreads();

#pragma unroll
        for (int ks = 0; ks < 32; ks += 16) {
            uint32_t aH[2][4], aL[2][4];
#pragma unroll
            for (int mt = 0; mt < 2; mt++) {
                int ar = warp_m * 32 + mt * 16 + (lane & 15);
                int ac = ks + (lane >> 4) * 8;
                ldm_x4(aH[mt], smem_u32(&Ah[ar][ac]));
                ldm_x4(aL[mt], smem_u32(&Al[ar][ac]));
            }
#pragma unroll
            for (int nt2 = 0; nt2 < 4; nt2++) {
                int br = ks + (lane & 15);
                int bc = warp_n * 64 + nt2 * 16 + (lane >> 4) * 8;
                uint32_t bH[4], bL[4];
                ldm_x4_t(bH, smem_u32(&Bh[br][bc]));
                ldm_x4_t(bL, smem_u32(&Bl[br][bc]));
#pragma unroll
                for (int mt = 0; mt < 2; mt++) {
                    mma_bf16(acc[mt][nt2 * 2 + 0], aH[mt], bH + 0);
                    mma_bf16(acc[mt][nt2 * 2 + 1], aH[mt], bH + 2);
                    mma_bf16(acc[mt][nt2 * 2 + 0], aH[mt], bL + 0);
                    mma_bf16(acc[mt][nt2 * 2 + 1], aH[mt], bL + 2);
                    mma_bf16(acc[mt][nt2 * 2 + 0], aL[mt], bH + 0);
                    mma_bf16(acc[mt][nt2 * 2 + 1], aL[mt], bH + 2);
                }
            }
        }
        __syncthreads();
    }

    const int g = lane >> 2, tg = lane & 3;
#pragma unroll
    for (int mt = 0; mt < 2; mt++) {
#pragma unroll
        for (int nt = 0; nt < 8; nt++) {
            int col = warp_n * 64 + nt * 8 + tg * 2;
            float b0 = __ldg(&bl[col]), b1 = __ldg(&bl[col + 1]);
            int row = row0 + warp_m * 32 + mt * 16 + g;
            if (row < nrows) {
                float v0 = acc[mt][nt][0] + b0;
                float v1 = acc[mt][nt][1] + b1;
                if (do_relu) { v0 = fmaxf(v0, 0.f); v1 = fmaxf(v1, 0.f); }
                *(float2*)(out + (size_t)row * HIDD + col) = make_float2(v0, v1);
            }
            int row2 = row + 8;
            if (row2 < nrows) {
                float v0 = acc[mt][nt][2] + b0;
                float v1 = acc[mt][nt][3] + b1;
                if (do_relu) { v0 = fmaxf(v0, 0.f); v1 = fmaxf(v1, 0.f); }
                *(float2*)(out + (size_t)row2 * HIDD + col) = make_float2(v0, v1);
            }
        }
    }
}

// ================= encoder: out = relu(x @ Wx + proj1[i1] + proj2[i2]) =================
__global__ __launch_bounds__(256, 2) void encoder2_kernel(
    const float* __restrict__ x, int Kx,
    const int* __restrict__ idx1, const float* __restrict__ proj1,
    const int* __restrict__ idx2, const float* __restrict__ proj2,
    const float* __restrict__ W,
    float* __restrict__ out, int nrows)
{
    __shared__ __align__(16) __nv_bfloat16 Ah[128][40];
    __shared__ __align__(16) __nv_bfloat16 Al[128][40];
    __shared__ __align__(16) __nv_bfloat16 Bh[32][136];
    __shared__ __align__(16) __nv_bfloat16 Bl[32][136];

    const int t = threadIdx.x;
    const int lane = t & 31;
    const int wid = t >> 5;
    const int warp_m = wid & 3;
    const int warp_n = wid >> 2;
    const int row0 = blockIdx.x * 128;

    float acc[2][8][4];
#pragma unroll
    for (int mt = 0; mt < 2; mt++)
#pragma unroll
        for (int nt = 0; nt < 8; nt++)
#pragma unroll
            for (int i = 0; i < 4; i++) acc[mt][nt][i] = 0.f;

    for (int k0 = 0; k0 < Kx; k0 += 32) {
#pragma unroll
        for (int i = 0; i < 4; i++) {
            int idx4 = t + 256 * i;
            int k4 = idx4 & 7, r = idx4 >> 3;
            int row = row0 + r;
            float4 v = make_float4(0.f, 0.f, 0.f, 0.f);
            if (row < nrows) v = *(const float4*)(x + (size_t)row * Kx + k0 + k4 * 4);
            int c = k4 * 4;
            split2(v.x, Ah[r][c + 0], Al[r][c + 0]);
            split2(v.y, Ah[r][c + 1], Al[r][c + 1]);
            split2(v.z, Ah[r][c + 2], Al[r][c + 2]);
            split2(v.w, Ah[r][c + 3], Al[r][c + 3]);
        }
#pragma unroll
        for (int i = 0; i < 4; i++) {
            int idx4 = t + 256 * i;
            int c4 = idx4 & 31, kk = idx4 >> 5;
            float4 v = *(const float4*)(W + (size_t)(k0 + kk) * HIDD + c4 * 4);
            int c = c4 * 4;
            split2(v.x, Bh[kk][c + 0], Bl[kk][c + 0]);
            split2(v.y, Bh[kk][c + 1], Bl[kk][c + 1]);
            split2(v.z, Bh[kk][c + 2], Bl[kk][c + 2]);
            split2(v.w, Bh[kk][c + 3], Bl[kk][c + 3]);
        }
        __syncthreads();

#pragma unroll
        for (int ks = 0; ks < 32; ks += 16) {
            uint32_t aH[2][4], aL[2][4];
#pragma unroll
            for (int mt = 0; mt < 2; mt++) {
                int ar = warp_m * 32 + mt * 16 + (lane & 15);
                int ac = ks + (lane >> 4) * 8;
                ldm_x4(aH[mt], smem_u32(&Ah[ar][ac]));
                ldm_x4(aL[mt], smem_u32(&Al[ar][ac]));
            }
#pragma unroll
            for (int nt2 = 0; nt2 < 4; nt2++) {
                int br = ks + (lane & 15);
                int bc = warp_n * 64 + nt2 * 16 + (lane >> 4) * 8;
                uint32_t bH[4], bL[4];
                ldm_x4_t(bH, smem_u32(&Bh[br][bc]));
                ldm_x4_t(bL, smem_u32(&Bl[br][bc]));
#pragma unroll
                for (int mt = 0; mt < 2; mt++) {
                    mma_bf16(acc[mt][nt2 * 2 + 0], aH[mt], bH + 0);
                    mma_bf16(acc[mt][nt2 * 2 + 1], aH[mt], bH + 2);
                    mma_bf16(acc[mt][nt2 * 2 + 0], aH[mt], bL + 0);
                    mma_bf16(acc[mt][nt2 * 2 + 1], aH[mt], bL + 2);
                    mma_bf16(acc[mt][nt2 * 2 + 0], aL[mt], bH + 0);
                    mma_bf16(acc[mt][nt2 * 2 + 1], aL[mt], bH + 2);
                }
            }
        }
        __syncthreads();
    }

    const int g = lane >> 2, tg = lane & 3;
#pragma unroll
    for (int mt = 0; mt < 2; mt++) {
#pragma unroll
        for (int nt = 0; nt < 8; nt++) {
            int col = warp_n * 64 + nt * 8 + tg * 2;
            int row = row0 + warp_m * 32 + mt * 16 + g;
            if (row < nrows) {
                const float* p1 = proj1 + (size_t)idx1[row] * HIDD;
                float a0 = p1[col], a1 = p1[col + 1];
                if (idx2) {
                    const float* p2 = proj2 + (size_t)idx2[row] * HIDD;
                    a0 += p2[col]; a1 += p2[col + 1];
                }
                float v0 = fmaxf(acc[mt][nt][0] + a0, 0.f);
                float v1 = fmaxf(acc[mt][nt][1] + a1, 0.f);
                *(float2*)(out + (size_t)row * HIDD + col) = make_float2(v0, v1);
            }
            int row2 = row + 8;
            if (row2 < nrows) {
                const float* p1 = proj1 + (size_t)idx1[row2] * HIDD;
                float a0 = p1[col], a1 = p1[col + 1];
                if (idx2) {
                    const float* p2 = proj2 + (size_t)idx2[row2] * HIDD;
                    a0 += p2[col]; a1 += p2[col + 1];
                }
                float v0 = fmaxf(acc[mt][nt][2] + a0, 0.f);
                float v1 = fmaxf(acc[mt][nt][3] + a1, 0.f);
                *(float2*)(out + (size_t)row2 * HIDD + col) = make_float2(v0, v1);
            }
        }
    }
}

// ---------------- launch ----------------
extern "C" void kernel_launch(void* const* d_in, const int* in_sizes, int n_in,
                              void* d_out, int out_size) {
    const float* x_pol    = (const float*)d_in[0];
    const int*   pol_sidx = (const int*)d_in[1];
    const float* x_comp   = (const float*)d_in[2];
    const int*   c_sidx   = (const int*)d_in[3];
    const int*   c_iidx   = (const int*)d_in[4];
    const int*   edge     = (const int*)d_in[5];
    const float* st_emb   = (const float*)d_in[6];
    const float* sec_emb  = (const float*)d_in[7];
    const float* ind_emb  = (const float*)d_in[8];
    const float* W_pol    = (const float*)d_in[9];
    const float* b_pol    = (const float*)d_in[10];
    const float* W_comp   = (const float*)d_in[11];
    const float* b_comp   = (const float*)d_in[12];
    const float* Wl1      = (const float*)d_in[13];
    const float* bl1      = (const float*)d_in[14];
    const float* Wr1      = (const float*)d_in[15];
    const float* Wl2      = (const float*)d_in[16];
    const float* bl2      = (const float*)d_in[17];
    const float* Wr2      = (const float*)d_in[18];
    float* out = (float*)d_out;

    const int E = in_sizes[5] / 2;
    const int* src = edge;
    const int* dst = edge + E;

    static float *p_h = nullptr, *p_h2, *p_mean, *p_sp, *p_secp, *p_ip;
    static int *p_cnt, *p_row, *p_cur, *p_csr, *p_blk;
    if (p_h == nullptr) {
        cudaGetSymbolAddress((void**)&p_h, g_h);
        cudaGetSymbolAddress((void**)&p_h2, g_h2);
        cudaGetSymbolAddress((void**)&p_mean, g_mean);
        cudaGetSymbolAddress((void**)&p_cnt, g_cnt_i);
        cudaGetSymbolAddress((void**)&p_row, g_row);
        cudaGetSymbolAddress((void**)&p_cur, g_cur);
        cudaGetSymbolAddress((void**)&p_csr, g_csr);
        cudaGetSymbolAddress((void**)&p_blk, g_blk);
        cudaGetSymbolAddress((void**)&p_sp, g_sproj);
        cudaGetSymbolAddress((void**)&p_secp, g_secproj);
        cudaGetSymbolAddress((void**)&p_ip, g_iproj);
    }

    const int NB = (NN + 255) / 256;  // 391

    // ---- CSR build (shared by both layers) ----
    cudaMemsetAsync(p_cnt, 0, NN * sizeof(int));
    count_int_kernel<<<(E + 255) / 256, 256>>>(dst, p_cnt, E);
    blk_reduce_kernel<<<NB, 256>>>(p_cnt, p_blk, NN);
    scan_blk_kernel<<<1, 32>>>(p_blk, NB);
    blk_scan_write_kernel<<<NB, 256>>>(p_cnt, p_blk, p_row, p_cur, NN);
    fill_csr_kernel<<<(E + 255) / 256, 256>>>(src, dst, p_cur, p_csr, E);

    // ---- embedding projections + encoders -> g_h ----
    embproj_kernel<<<(27136 + 255) / 256, 256>>>(st_emb, sec_emb, ind_emb,
                                                 W_pol, b_pol, W_comp, b_comp,
                                                 p_sp, p_secp, p_ip);
    encoder2_kernel<<<(NP + 127) / 128, 256>>>(x_pol, 64, pol_sidx, p_sp,
                                               (const int*)nullptr, (const float*)nullptr,
                                               W_pol, p_h, NP);
    encoder2_kernel<<<(NC + 127) / 128, 256>>>(x_comp, 96, c_sidx, p_secp,
                                               c_iidx, p_ip,
                                               W_comp, p_h + (size_t)NP * HIDD, NC);

    // ---- SAGE layer 1 ----
    gather_mean_kernel<<<(NN * 32 + 255) / 256, 256>>>(p_h, p_mean);
    sage_mma_kernel<<<(NN + 127) / 128, 256>>>(p_h, Wl1, bl1, Wr1, p_h2, NN, 1);

    // ---- SAGE layer 2 ----
    gather_mean_kernel<<<(NN * 32 + 255) / 256, 256>>>(p_h2, p_mean);
    sage_mma_kernel<<<(NN + 127) / 128, 256>>>(p_h2, Wl2, bl2, Wr2, out, NN, 0);
}

// round 7
// speedup vs baseline: 2.8612x; 1.0083x over previous
#include <cuda_runtime.h>
#include <cuda_bf16.h>
#include <cuda_fp16.h>
#include <cstdint>

#define NP 20000
#define NC 80000
#define NN 100000
#define HIDD 128
#define EMAX 1600000

// ---------------- scratch (static device globals; no allocation) ----------------
__device__ float  g_h[(size_t)NN * HIDD];      // layer input features (fp32)
__device__ float  g_h2[(size_t)NN * HIDD];     // layer-1 output (fp32)
__device__ __half g_hf[(size_t)NN * HIDD];     // fp16 copy of current layer input (gather payload)
__device__ float  g_mean[(size_t)NN * HIDD];   // aggregated mean per node
__device__ int    g_cnt_i[NN];                 // in-degree
__device__ int    g_row[NN];                   // CSR row starts
__device__ int    g_cur[NN];                   // fill cursors
__device__ int    g_csr[EMAX];                 // CSR src ids
__device__ int    g_blk[512];                  // block sums for scan
__device__ float  g_sproj[50 * HIDD];
__device__ float  g_secproj[12 * HIDD];
__device__ float  g_iproj[150 * HIDD];

// ---------------- helpers ----------------
__device__ __forceinline__ uint32_t smem_u32(const void* p) {
    return (uint32_t)__cvta_generic_to_shared(p);
}
__device__ __forceinline__ void ldm_x4(uint32_t* r, uint32_t addr) {
    asm volatile("ldmatrix.sync.aligned.m8n8.x4.shared.b16 {%0,%1,%2,%3},[%4];"
                 : "=r"(r[0]), "=r"(r[1]), "=r"(r[2]), "=r"(r[3]) : "r"(addr));
}
__device__ __forceinline__ void ldm_x4_t(uint32_t* r, uint32_t addr) {
    asm volatile("ldmatrix.sync.aligned.m8n8.x4.trans.shared.b16 {%0,%1,%2,%3},[%4];"
                 : "=r"(r[0]), "=r"(r[1]), "=r"(r[2]), "=r"(r[3]) : "r"(addr));
}
__device__ __forceinline__ void mma_bf16(float* d, const uint32_t* a, const uint32_t* b) {
    asm volatile("mma.sync.aligned.m16n8k16.row.col.f32.bf16.bf16.f32 "
                 "{%0,%1,%2,%3},{%4,%5,%6,%7},{%8,%9},{%0,%1,%2,%3};"
                 : "+f"(d[0]), "+f"(d[1]), "+f"(d[2]), "+f"(d[3])
                 : "r"(a[0]), "r"(a[1]), "r"(a[2]), "r"(a[3]), "r"(b[0]), "r"(b[1]));
}
__device__ __forceinline__ void split2(float v, __nv_bfloat16& hi, __nv_bfloat16& lo) {
    hi = __float2bfloat16(v);
    lo = __float2bfloat16(v - __bfloat162float(hi));
}

// ---------------- CSR build ----------------
__global__ void count_int_kernel(const int* __restrict__ dst, int* cnt, int E) {
    int e = blockIdx.x * blockDim.x + threadIdx.x;
    if (e < E) atomicAdd(&cnt[dst[e]], 1);
}
__global__ void blk_reduce_kernel(const int* __restrict__ cnt, int* blk, int n) {
    __shared__ int s[256];
    int idx = blockIdx.x * 256 + threadIdx.x;
    s[threadIdx.x] = (idx < n) ? cnt[idx] : 0;
    __syncthreads();
    for (int off = 128; off > 0; off >>= 1) {
        if (threadIdx.x < off) s[threadIdx.x] += s[threadIdx.x + off];
        __syncthreads();
    }
    if (threadIdx.x == 0) blk[blockIdx.x] = s[0];
}
__global__ void scan_blk_kernel(int* blk, int nb) {
    if (threadIdx.x == 0 && blockIdx.x == 0) {
        int run = 0;
        for (int b = 0; b < nb; b++) { int t = blk[b]; blk[b] = run; run += t; }
    }
}
__global__ void blk_scan_write_kernel(const int* __restrict__ cnt, const int* __restrict__ blk,
                                      int* row, int* cur, int n) {
    __shared__ int s[256];
    int t = threadIdx.x;
    int idx = blockIdx.x * 256 + t;
    int v = (idx < n) ? cnt[idx] : 0;
    s[t] = v;
    __syncthreads();
#pragma unroll
    for (int off = 1; off < 256; off <<= 1) {
        int x = (t >= off) ? s[t - off] : 0;
        __syncthreads();
        s[t] += x;
        __syncthreads();
    }
    if (idx < n) {
        int excl = s[t] - v + blk[blockIdx.x];
        row[idx] = excl;
        cur[idx] = excl;
    }
}
__global__ void fill_csr_kernel(const int* __restrict__ src, const int* __restrict__ dst,
                                int* cur, int* csr, int E) {
    int e = blockIdx.x * blockDim.x + threadIdx.x;
    if (e < E) {
        int slot = atomicAdd(&cur[dst[e]], 1);
        csr[slot] = src[e];
    }
}

// ---------------- warp-per-node gather + mean (fp16 payload) ----------------
__global__ __launch_bounds__(256) void gather_mean_kernel(const __half* __restrict__ hsrc,
                                                          float* __restrict__ mout) {
    int w = (blockIdx.x * blockDim.x + threadIdx.x) >> 5;
    int lane = threadIdx.x & 31;
    if (w >= NN) return;
    int beg = g_row[w];
    int n = g_cnt_i[w];
    float ax = 0.f, ay = 0.f, az = 0.f, aw = 0.f;
    int i = 0;
    for (; i + 4 <= n; i += 4) {
        int s0 = __ldg(&g_csr[beg + i + 0]);
        int s1 = __ldg(&g_csr[beg + i + 1]);
        int s2 = __ldg(&g_csr[beg + i + 2]);
        int s3 = __ldg(&g_csr[beg + i + 3]);
        uint2 u0 = *(const uint2*)(hsrc + (size_t)s0 * HIDD + lane * 4);
        uint2 u1 = *(const uint2*)(hsrc + (size_t)s1 * HIDD + lane * 4);
        uint2 u2 = *(const uint2*)(hsrc + (size_t)s2 * HIDD + lane * 4);
        uint2 u3 = *(const uint2*)(hsrc + (size_t)s3 * HIDD + lane * 4);
        float2 a0 = __half22float2(*(__half2*)&u0.x), b0 = __half22float2(*(__half2*)&u0.y);
        float2 a1 = __half22float2(*(__half2*)&u1.x), b1 = __half22float2(*(__half2*)&u1.y);
        float2 a2 = __half22float2(*(__half2*)&u2.x), b2 = __half22float2(*(__half2*)&u2.y);
        float2 a3 = __half22float2(*(__half2*)&u3.x), b3 = __half22float2(*(__half2*)&u3.y);
        ax += (a0.x + a1.x) + (a2.x + a3.x);
        ay += (a0.y + a1.y) + (a2.y + a3.y);
        az += (b0.x + b1.x) + (b2.x + b3.x);
        aw += (b0.y + b1.y) + (b2.y + b3.y);
    }
    for (; i < n; i++) {
        int s0 = __ldg(&g_csr[beg + i]);
        uint2 u0 = *(const uint2*)(hsrc + (size_t)s0 * HIDD + lane * 4);
        float2 a0 = __half22float2(*(__half2*)&u0.x), b0 = __half22float2(*(__half2*)&u0.y);
        ax += a0.x; ay += a0.y; az += b0.x; aw += b0.y;
    }
    float inv = 1.f / fmaxf((float)n, 1.f);
    float4 r = make_float4(ax * inv, ay * inv, az * inv, aw * inv);
    *(float4*)(mout + (size_t)w * HIDD + lane * 4) = r;
}

// ---------------- embedding projection tables ----------------
__global__ void embproj_kernel(const float* __restrict__ st_emb,
                               const float* __restrict__ sec_emb,
                               const float* __restrict__ ind_emb,
                               const float* __restrict__ W_pol,
                               const float* __restrict__ b_pol,
                               const float* __restrict__ W_comp,
                               const float* __restrict__ b_comp,
                               float* __restrict__ sproj, float* __restrict__ secproj,
                               float* __restrict__ iproj) {
    int i = blockIdx.x * blockDim.x + threadIdx.x;
    if (i >= 27136) return;
    const float* emb; const float* W; const float* bias; float* outp; int r, c;
    if (i < 6400) {
        r = i >> 7; c = i & 127;
        emb = st_emb + r * 8; W = W_pol + 64 * HIDD; bias = b_pol; outp = sproj + i;
    } else if (i < 7936) {
        int j = i - 6400; r = j >> 7; c = j & 127;
        emb = sec_emb + r * 8; W = W_comp + 96 * HIDD; bias = b_comp; outp = secproj + j;
    } else {
        int j = i - 7936; r = j >> 7; c = j & 127;
        emb = ind_emb + r * 8; W = W_comp + 104 * HIDD; bias = nullptr; outp = iproj + j;
    }
    float s = bias ? bias[c] : 0.f;
#pragma unroll
    for (int j = 0; j < 8; j++) s = fmaf(emb[j], W[j * HIDD + c], s);
    *outp = s;
}

// ================= split-bf16 tensor-core SAGE GEMM =================
// out[nrows,128] = act( [g_mean | hin] @ [Wl;Wr] + bl ); optional fp16 copy of output
__global__ __launch_bounds__(256, 2) void sage_mma_kernel(
    const float* __restrict__ hin,
    const float* __restrict__ Wl, const float* __restrict__ bl,
    const float* __restrict__ Wr,
    float* __restrict__ out, __half* __restrict__ hf_out, int nrows, int do_relu)
{
    __shared__ __align__(16) __nv_bfloat16 Ah[128][40];
    __shared__ __align__(16) __nv_bfloat16 Al[128][40];
    __shared__ __align__(16) __nv_bfloat16 Bh[32][136];
    __shared__ __align__(16) __nv_bfloat16 Bl[32][136];

    const int t = threadIdx.x;
    const int lane = t & 31;
    const int wid = t >> 5;
    const int warp_m = wid & 3;
    const int warp_n = wid >> 2;
    const int row0 = blockIdx.x * 128;

    float acc[2][8][4];
#pragma unroll
    for (int mt = 0; mt < 2; mt++)
#pragma unroll
        for (int nt = 0; nt < 8; nt++)
#pragma unroll
            for (int i = 0; i < 4; i++) acc[mt][nt][i] = 0.f;

    for (int k0 = 0; k0 < 256; k0 += 32) {
        const bool left = (k0 < 128);
#pragma unroll
        for (int i = 0; i < 4; i++) {
            int idx4 = t + 256 * i;
            int k4 = idx4 & 7, r = idx4 >> 3;
            int row = row0 + r;
            float4 v = make_float4(0.f, 0.f, 0.f, 0.f);
            if (row < nrows) {
                int kk = k0 + k4 * 4;
                if (left) v = *(const float4*)(g_mean + (size_t)row * HIDD + kk);
                else      v = *(const float4*)(hin + (size_t)row * HIDD + (kk - 128));
            }
            int c = k4 * 4;
            split2(v.x, Ah[r][c + 0], Al[r][c + 0]);
            split2(v.y, Ah[r][c + 1], Al[r][c + 1]);
            split2(v.z, Ah[r][c + 2], Al[r][c + 2]);
            split2(v.w, Ah[r][c + 3], Al[r][c + 3]);
        }
#pragma unroll
        for (int i = 0; i < 4; i++) {
            int idx4 = t + 256 * i;
            int c4 = idx4 & 31, kk = idx4 >> 5;
            int gk = k0 + kk;
            const float* B = left ? (Wl + (size_t)gk * HIDD) : (Wr + (size_t)(gk - 128) * HIDD);
            float4 v = *(const float4*)(B + c4 * 4);
            int c = c4 * 4;
            split2(v.x, Bh[kk][c + 0], Bl[kk][c + 0]);
            split2(v.y, Bh[kk][c + 1], Bl[kk][c + 1]);
            split2(v.z, Bh[kk][c + 2], Bl[kk][c + 2]);
            split2(v.w, Bh[kk][c + 3], Bl[kk][c + 3]);
        }
        __syncthreads();

#pragma unroll
        for (int ks = 0; ks < 32; ks += 16) {
            uint32_t aH[2][4], aL[2][4];
#pragma unroll
            for (int mt = 0; mt < 2; mt++) {
                int ar = warp_m * 32 + mt * 16 + (lane & 15);
                int ac = ks + (lane >> 4) * 8;
                ldm_x4(aH[mt], smem_u32(&Ah[ar][ac]));
                ldm_x4(aL[mt], smem_u32(&Al[ar][ac]));
            }
#pragma unroll
            for (int nt2 = 0; nt2 < 4; nt2++) {
                int br = ks + (lane & 15);
                int bc = warp_n * 64 + nt2 * 16 + (lane >> 4) * 8;
                uint32_t bH[4], bL[4];
                ldm_x4_t(bH, smem_u32(&Bh[br][bc]));
                ldm_x4_t(bL, smem_u32(&Bl[br][bc]));
#pragma unroll
                for (int mt = 0; mt < 2; mt++) {
                    mma_bf16(acc[mt][nt2 * 2 + 0], aH[mt], bH + 0);
                    mma_bf16(acc[mt][nt2 * 2 + 1], aH[mt], bH + 2);
                    mma_bf16(acc[mt][nt2 * 2 + 0], aH[mt], bL + 0);
                    mma_bf16(acc[mt][nt2 * 2 + 1], aH[mt], bL + 2);
                    mma_bf16(acc[mt][nt2 * 2 + 0], aL[mt], bH + 0);
                    mma_bf16(acc[mt][nt2 * 2 + 1], aL[mt], bH + 2);
                }
            }
        }
        __syncthreads();
    }

    const int g = lane >> 2, tg = lane & 3;
#pragma unroll
    for (int mt = 0; mt < 2; mt++) {
#pragma unroll
        for (int nt = 0; nt < 8; nt++) {
            int col = warp_n * 64 + nt * 8 + tg * 2;
            float b0 = __ldg(&bl[col]), b1 = __ldg(&bl[col + 1]);
            int row = row0 + warp_m * 32 + mt * 16 + g;
            if (row < nrows) {
                float v0 = acc[mt][nt][0] + b0;
                float v1 = acc[mt][nt][1] + b1;
                if (do_relu) { v0 = fmaxf(v0, 0.f); v1 = fmaxf(v1, 0.f); }
                *(float2*)(out + (size_t)row * HIDD + col) = make_float2(v0, v1);
                if (hf_out)
                    *(__half2*)(hf_out + (size_t)row * HIDD + col) = __floats2half2_rn(v0, v1);
            }
            int row2 = row + 8;
            if (row2 < nrows) {
                float v0 = acc[mt][nt][2] + b0;
                float v1 = acc[mt][nt][3] + b1;
                if (do_relu) { v0 = fmaxf(v0, 0.f); v1 = fmaxf(v1, 0.f); }
                *(float2*)(out + (size_t)row2 * HIDD + col) = make_float2(v0, v1);
                if (hf_out)
                    *(__half2*)(hf_out + (size_t)row2 * HIDD + col) = __floats2half2_rn(v0, v1);
            }
        }
    }
}

// ================= encoder: out = relu(x @ Wx + proj1[i1] + proj2[i2]) =================
__global__ __launch_bounds__(256, 2) void encoder2_kernel(
    const float* __restrict__ x, int Kx,
    const int* __restrict__ idx1, const float* __restrict__ proj1,
    const int* __restrict__ idx2, const float* __restrict__ proj2,
    const float* __restrict__ W,
    float* __restrict__ out, __half* __restrict__ hf_out, int nrows)
{
    __shared__ __align__(16) __nv_bfloat16 Ah[128][40];
    __shared__ __align__(16) __nv_bfloat16 Al[128][40];
    __shared__ __align__(16) __nv_bfloat16 Bh[32][136];
    __shared__ __align__(16) __nv_bfloat16 Bl[32][136];

    const int t = threadIdx.x;
    const int lane = t & 31;
    const int wid = t >> 5;
    const int warp_m = wid & 3;
    const int warp_n = wid >> 2;
    const int row0 = blockIdx.x * 128;

    float acc[2][8][4];
#pragma unroll
    for (int mt = 0; mt < 2; mt++)
#pragma unroll
        for (int nt = 0; nt < 8; nt++)
#pragma unroll
            for (int i = 0; i < 4; i++) acc[mt][nt][i] = 0.f;

    for (int k0 = 0; k0 < Kx; k0 += 32) {
#pragma unroll
        for (int i = 0; i < 4; i++) {
            int idx4 = t + 256 * i;
            int k4 = idx4 & 7, r = idx4 >> 3;
            int row = row0 + r;
            float4 v = make_float4(0.f, 0.f, 0.f, 0.f);
            if (row < nrows) v = *(const float4*)(x + (size_t)row * Kx + k0 + k4 * 4);
            int c = k4 * 4;
            split2(v.x, Ah[r][c + 0], Al[r][c + 0]);
            split2(v.y, Ah[r][c + 1], Al[r][c + 1]);
            split2(v.z, Ah[r][c + 2], Al[r][c + 2]);
            split2(v.w, Ah[r][c + 3], Al[r][c + 3]);
        }
#pragma unroll
        for (int i = 0; i < 4; i++) {
            int idx4 = t + 256 * i;
            int c4 = idx4 & 31, kk = idx4 >> 5;
            float4 v = *(const float4*)(W + (size_t)(k0 + kk) * HIDD + c4 * 4);
            int c = c4 * 4;
            split2(v.x, Bh[kk][c + 0], Bl[kk][c + 0]);
            split2(v.y, Bh[kk][c + 1], Bl[kk][c + 1]);
            split2(v.z, Bh[kk][c + 2], Bl[kk][c + 2]);
            split2(v.w, Bh[kk][c + 3], Bl[kk][c + 3]);
        }
        __syncthreads();

#pragma unroll
        for (int ks = 0; ks < 32; ks += 16) {
            uint32_t aH[2][4], aL[2][4];
#pragma unroll
            for (int mt = 0; mt < 2; mt++) {
                int ar = warp_m * 32 + mt * 16 + (lane & 15);
                int ac = ks + (lane >> 4) * 8;
                ldm_x4(aH[mt], smem_u32(&Ah[ar][ac]));
                ldm_x4(aL[mt], smem_u32(&Al[ar][ac]));
            }
#pragma unroll
            for (int nt2 = 0; nt2 < 4; nt2++) {
                int br = ks + (lane & 15);
                int bc = warp_n * 64 + nt2 * 16 + (lane >> 4) * 8;
                uint32_t bH[4], bL[4];
                ldm_x4_t(bH, smem_u32(&Bh[br][bc]));
                ldm_x4_t(bL, smem_u32(&Bl[br][bc]));
#pragma unroll
                for (int mt = 0; mt < 2; mt++) {
                    mma_bf16(acc[mt][nt2 * 2 + 0], aH[mt], bH + 0);
                    mma_bf16(acc[mt][nt2 * 2 + 1], aH[mt], bH + 2);
                    mma_bf16(acc[mt][nt2 * 2 + 0], aH[mt], bL + 0);
                    mma_bf16(acc[mt][nt2 * 2 + 1], aH[mt], bL + 2);
                    mma_bf16(acc[mt][nt2 * 2 + 0], aL[mt], bH + 0);
                    mma_bf16(acc[mt][nt2 * 2 + 1], aL[mt], bH + 2);
                }
            }
        }
        __syncthreads();
    }

    const int g = lane >> 2, tg = lane & 3;
#pragma unroll
    for (int mt = 0; mt < 2; mt++) {
#pragma unroll
        for (int nt = 0; nt < 8; nt++) {
            int col = warp_n * 64 + nt * 8 + tg * 2;
            int row = row0 + warp_m * 32 + mt * 16 + g;
            if (row < nrows) {
                const float* p1 = proj1 + (size_t)idx1[row] * HIDD;
                float a0 = p1[col], a1 = p1[col + 1];
                if (idx2) {
                    const float* p2 = proj2 + (size_t)idx2[row] * HIDD;
                    a0 += p2[col]; a1 += p2[col + 1];
                }
                float v0 = fmaxf(acc[mt][nt][0] + a0, 0.f);
                float v1 = fmaxf(acc[mt][nt][1] + a1, 0.f);
                *(float2*)(out + (size_t)row * HIDD + col) = make_float2(v0, v1);
                *(__half2*)(hf_out + (size_t)row * HIDD + col) = __floats2half2_rn(v0, v1);
            }
            int row2 = row + 8;
            if (row2 < nrows) {
                const float* p1 = proj1 + (size_t)idx1[row2] * HIDD;
                float a0 = p1[col], a1 = p1[col + 1];
                if (idx2) {
                    const float* p2 = proj2 + (size_t)idx2[row2] * HIDD;
                    a0 += p2[col]; a1 += p2[col + 1];
                }
                float v0 = fmaxf(acc[mt][nt][2] + a0, 0.f);
                float v1 = fmaxf(acc[mt][nt][3] + a1, 0.f);
                *(float2*)(out + (size_t)row2 * HIDD + col) = make_float2(v0, v1);
                *(__half2*)(hf_out + (size_t)row2 * HIDD + col) = __floats2half2_rn(v0, v1);
            }
        }
    }
}

// ---------------- launch ----------------
extern "C" void kernel_launch(void* const* d_in, const int* in_sizes, int n_in,
                              void* d_out, int out_size) {
    const float* x_pol    = (const float*)d_in[0];
    const int*   pol_sidx = (const int*)d_in[1];
    const float* x_comp   = (const float*)d_in[2];
    const int*   c_sidx   = (const int*)d_in[3];
    const int*   c_iidx   = (const int*)d_in[4];
    const int*   edge     = (const int*)d_in[5];
    const float* st_emb   = (const float*)d_in[6];
    const float* sec_emb  = (const float*)d_in[7];
    const float* ind_emb  = (const float*)d_in[8];
    const float* W_pol    = (const float*)d_in[9];
    const float* b_pol    = (const float*)d_in[10];
    const float* W_comp   = (const float*)d_in[11];
    const float* b_comp   = (const float*)d_in[12];
    const float* Wl1      = (const float*)d_in[13];
    const float* bl1      = (const float*)d_in[14];
    const float* Wr1      = (const float*)d_in[15];
    const float* Wl2      = (const float*)d_in[16];
    const float* bl2      = (const float*)d_in[17];
    const float* Wr2      = (const float*)d_in[18];
    float* out = (float*)d_out;

    const int E = in_sizes[5] / 2;
    const int* src = edge;
    const int* dst = edge + E;

    static float *p_h = nullptr, *p_h2, *p_mean, *p_sp, *p_secp, *p_ip;
    static __half* p_hf;
    static int *p_cnt, *p_row, *p_cur, *p_csr, *p_blk;
    if (p_h == nullptr) {
        cudaGetSymbolAddress((void**)&p_h, g_h);
        cudaGetSymbolAddress((void**)&p_h2, g_h2);
        cudaGetSymbolAddress((void**)&p_hf, g_hf);
        cudaGetSymbolAddress((void**)&p_mean, g_mean);
        cudaGetSymbolAddress((void**)&p_cnt, g_cnt_i);
        cudaGetSymbolAddress((void**)&p_row, g_row);
        cudaGetSymbolAddress((void**)&p_cur, g_cur);
        cudaGetSymbolAddress((void**)&p_csr, g_csr);
        cudaGetSymbolAddress((void**)&p_blk, g_blk);
        cudaGetSymbolAddress((void**)&p_sp, g_sproj);
        cudaGetSymbolAddress((void**)&p_secp, g_secproj);
        cudaGetSymbolAddress((void**)&p_ip, g_iproj);
    }

    const int NB = (NN + 255) / 256;  // 391

    // ---- CSR build (shared by both layers) ----
    cudaMemsetAsync(p_cnt, 0, NN * sizeof(int));
    count_int_kernel<<<(E + 255) / 256, 256>>>(dst, p_cnt, E);
    blk_reduce_kernel<<<NB, 256>>>(p_cnt, p_blk, NN);
    scan_blk_kernel<<<1, 32>>>(p_blk, NB);
    blk_scan_write_kernel<<<NB, 256>>>(p_cnt, p_blk, p_row, p_cur, NN);
    fill_csr_kernel<<<(E + 255) / 256, 256>>>(src, dst, p_cur, p_csr, E);

    // ---- embedding projections + encoders -> g_h (+fp16 copy) ----
    embproj_kernel<<<(27136 + 255) / 256, 256>>>(st_emb, sec_emb, ind_emb,
                                                 W_pol, b_pol, W_comp, b_comp,
                                                 p_sp, p_secp, p_ip);
    encoder2_kernel<<<(NP + 127) / 128, 256>>>(x_pol, 64, pol_sidx, p_sp,
                                               (const int*)nullptr, (const float*)nullptr,
                                               W_pol, p_h, p_hf, NP);
    encoder2_kernel<<<(NC + 127) / 128, 256>>>(x_comp, 96, c_sidx, p_secp,
                                               c_iidx, p_ip,
                                               W_comp, p_h + (size_t)NP * HIDD,
                                               p_hf + (size_t)NP * HIDD, NC);

    // ---- SAGE layer 1 ----
    gather_mean_kernel<<<(NN * 32 + 255) / 256, 256>>>(p_hf, p_mean);
    sage_mma_kernel<<<(NN + 127) / 128, 256>>>(p_h, Wl1, bl1, Wr1, p_h2, p_hf, NN, 1);

    // ---- SAGE layer 2 ----
    gather_mean_kernel<<<(NN * 32 + 255) / 256, 256>>>(p_hf, p_mean);
    sage_mma_kernel<<<(NN + 127) / 128, 256>>>(p_h2, Wl2, bl2, Wr2, out, (__half*)nullptr, NN, 0);
}

// round 9
// speedup vs baseline: 3.8585x; 1.3486x over previous
#include <cuda_runtime.h>
#include <cuda_fp16.h>
#include <cstdint>

#define NP 20000
#define NC 80000
#define NN 100000
#define HIDD 128
#define EMAX 1600000

// ---------------- scratch (static device globals; no allocation) ----------------
__device__ __half g_hf[(size_t)NN * HIDD];     // current layer features (fp16)
__device__ __half g_meanh[(size_t)NN * HIDD];  // aggregated mean per node (fp16)
__device__ int    g_cnt_i[NN];                 // in-degree
__device__ int    g_row[NN];                   // CSR row starts
__device__ int    g_cur[NN];                   // fill cursors
__device__ int    g_csr[EMAX];                 // CSR src ids
__device__ int    g_blk[512];                  // block sums for scan
__device__ float  g_sproj[50 * HIDD];
__device__ float  g_secproj[12 * HIDD];
__device__ float  g_iproj[150 * HIDD];

// ---------------- helpers ----------------
__device__ __forceinline__ uint32_t smem_u32(const void* p) {
    return (uint32_t)__cvta_generic_to_shared(p);
}
__device__ __forceinline__ void ldm_x4(uint32_t* r, uint32_t addr) {
    asm volatile("ldmatrix.sync.aligned.m8n8.x4.shared.b16 {%0,%1,%2,%3},[%4];"
                 : "=r"(r[0]), "=r"(r[1]), "=r"(r[2]), "=r"(r[3]) : "r"(addr));
}
__device__ __forceinline__ void ldm_x4_t(uint32_t* r, uint32_t addr) {
    asm volatile("ldmatrix.sync.aligned.m8n8.x4.trans.shared.b16 {%0,%1,%2,%3},[%4];"
                 : "=r"(r[0]), "=r"(r[1]), "=r"(r[2]), "=r"(r[3]) : "r"(addr));
}
__device__ __forceinline__ void mma_f16(float* d, const uint32_t* a, const uint32_t* b) {
    asm volatile("mma.sync.aligned.m16n8k16.row.col.f32.f16.f16.f32 "
                 "{%0,%1,%2,%3},{%4,%5,%6,%7},{%8,%9},{%0,%1,%2,%3};"
                 : "+f"(d[0]), "+f"(d[1]), "+f"(d[2]), "+f"(d[3])
                 : "r"(a[0]), "r"(a[1]), "r"(a[2]), "r"(a[3]), "r"(b[0]), "r"(b[1]));
}

// ---------------- CSR build ----------------
__global__ void count_int_kernel(const int* __restrict__ dst, int* cnt, int E) {
    int e = blockIdx.x * blockDim.x + threadIdx.x;
    if (e < E) atomicAdd(&cnt[dst[e]], 1);
}
__global__ void blk_reduce_kernel(const int* __restrict__ cnt, int* blk, int n) {
    __shared__ int s[256];
    int idx = blockIdx.x * 256 + threadIdx.x;
    s[threadIdx.x] = (idx < n) ? cnt[idx] : 0;
    __syncthreads();
    for (int off = 128; off > 0; off >>= 1) {
        if (threadIdx.x < off) s[threadIdx.x] += s[threadIdx.x + off];
        __syncthreads();
    }
    if (threadIdx.x == 0) blk[blockIdx.x] = s[0];
}
__global__ void scan_blk_kernel(int* blk, int nb) {
    if (threadIdx.x == 0 && blockIdx.x == 0) {
        int run = 0;
        for (int b = 0; b < nb; b++) { int t = blk[b]; blk[b] = run; run += t; }
    }
}
__global__ void blk_scan_write_kernel(const int* __restrict__ cnt, const int* __restrict__ blk,
                                      int* row, int* cur, int n) {
    __shared__ int s[256];
    int t = threadIdx.x;
    int idx = blockIdx.x * 256 + t;
    int v = (idx < n) ? cnt[idx] : 0;
    s[t] = v;
    __syncthreads();
#pragma unroll
    for (int off = 1; off < 256; off <<= 1) {
        int x = (t >= off) ? s[t - off] : 0;
        __syncthreads();
        s[t] += x;
        __syncthreads();
    }
    if (idx < n) {
        int excl = s[t] - v + blk[blockIdx.x];
        row[idx] = excl;
        cur[idx] = excl;
    }
}
__global__ void fill_csr_kernel(const int* __restrict__ src, const int* __restrict__ dst,
                                int* cur, int* csr, int E) {
    int e = blockIdx.x * blockDim.x + threadIdx.x;
    if (e < E) {
        int slot = atomicAdd(&cur[dst[e]], 1);
        csr[slot] = src[e];
    }
}

// ---------------- warp-per-node gather + mean (fp16 in, fp16 out) ----------------
__global__ __launch_bounds__(256) void gather_mean_kernel(const __half* __restrict__ hsrc,
                                                          __half* __restrict__ mout) {
    int w = (blockIdx.x * blockDim.x + threadIdx.x) >> 5;
    int lane = threadIdx.x & 31;
    if (w >= NN) return;
    int beg = g_row[w];
    int n = g_cnt_i[w];
    float ax = 0.f, ay = 0.f, az = 0.f, aw = 0.f;
    int i = 0;
    for (; i + 4 <= n; i += 4) {
        int s0 = __ldg(&g_csr[beg + i + 0]);
        int s1 = __ldg(&g_csr[beg + i + 1]);
        int s2 = __ldg(&g_csr[beg + i + 2]);
        int s3 = __ldg(&g_csr[beg + i + 3]);
        uint2 u0 = *(const uint2*)(hsrc + (size_t)s0 * HIDD + lane * 4);
        uint2 u1 = *(const uint2*)(hsrc + (size_t)s1 * HIDD + lane * 4);
        uint2 u2 = *(const uint2*)(hsrc + (size_t)s2 * HIDD + lane * 4);
        uint2 u3 = *(const uint2*)(hsrc + (size_t)s3 * HIDD + lane * 4);
        float2 a0 = __half22float2(*(__half2*)&u0.x), b0 = __half22float2(*(__half2*)&u0.y);
        float2 a1 = __half22float2(*(__half2*)&u1.x), b1 = __half22float2(*(__half2*)&u1.y);
        float2 a2 = __half22float2(*(__half2*)&u2.x), b2 = __half22float2(*(__half2*)&u2.y);
        float2 a3 = __half22float2(*(__half2*)&u3.x), b3 = __half22float2(*(__half2*)&u3.y);
        ax += (a0.x + a1.x) + (a2.x + a3.x);
        ay += (a0.y + a1.y) + (a2.y + a3.y);
        az += (b0.x + b1.x) + (b2.x + b3.x);
        aw += (b0.y + b1.y) + (b2.y + b3.y);
    }
    for (; i < n; i++) {
        int s0 = __ldg(&g_csr[beg + i]);
        uint2 u0 = *(const uint2*)(hsrc + (size_t)s0 * HIDD + lane * 4);
        float2 a0 = __half22float2(*(__half2*)&u0.x), b0 = __half22float2(*(__half2*)&u0.y);
        ax += a0.x; ay += a0.y; az += b0.x; aw += b0.y;
    }
    float inv = 1.f / fmaxf((float)n, 1.f);
    uint2 r;
    *(__half2*)&r.x = __floats2half2_rn(ax * inv, ay * inv);
    *(__half2*)&r.y = __floats2half2_rn(az * inv, aw * inv);
    *(uint2*)(mout + (size_t)w * HIDD + lane * 4) = r;
}

// ---------------- embedding projection tables ----------------
__global__ void embproj_kernel(const float* __restrict__ st_emb,
                               const float* __restrict__ sec_emb,
                               const float* __restrict__ ind_emb,
                               const float* __restrict__ W_pol,
                               const float* __restrict__ b_pol,
                               const float* __restrict__ W_comp,
                               const float* __restrict__ b_comp,
                               float* __restrict__ sproj, float* __restrict__ secproj,
                               float* __restrict__ iproj) {
    int i = blockIdx.x * blockDim.x + threadIdx.x;
    if (i >= 27136) return;
    const float* emb; const float* W; const float* bias; float* outp; int r, c;
    if (i < 6400) {
        r = i >> 7; c = i & 127;
        emb = st_emb + r * 8; W = W_pol + 64 * HIDD; bias = b_pol; outp = sproj + i;
    } else if (i < 7936) {
        int j = i - 6400; r = j >> 7; c = j & 127;
        emb = sec_emb + r * 8; W = W_comp + 96 * HIDD; bias = b_comp; outp = secproj + j;
    } else {
        int j = i - 7936; r = j >> 7; c = j & 127;
        emb = ind_emb + r * 8; W = W_comp + 104 * HIDD; bias = nullptr; outp = iproj + j;
    }
    float s = bias ? bias[c] : 0.f;
#pragma unroll
    for (int j = 0; j < 8; j++) s = fmaf(emb[j], W[j * HIDD + c], s);
    *outp = s;
}

// ================= single-pass fp16 SAGE GEMM =================
// acc = [g_meanh | g_hf] @ [Wl;Wr] + bl ; relu opt; writes fp32 out and/or fp16 hf_out
__global__ __launch_bounds__(256, 2) void sage_mma_kernel(
    const __half* __restrict__ meanh, const __half* __restrict__ hf,
    const float* __restrict__ Wl, const float* __restrict__ bl,
    const float* __restrict__ Wr,
    float* __restrict__ out, __half* __restrict__ hf_out, int nrows, int do_relu)
{
    __shared__ __align__(16) __half As[128][40];
    __shared__ __align__(16) __half Bs[32][136];

    const int t = threadIdx.x;
    const int lane = t & 31;
    const int wid = t >> 5;
    const int warp_m = wid & 3;
    const int warp_n = wid >> 2;
    const int row0 = blockIdx.x * 128;

    float acc[2][8][4];
#pragma unroll
    for (int mt = 0; mt < 2; mt++)
#pragma unroll
        for (int nt = 0; nt < 8; nt++)
#pragma unroll
            for (int i = 0; i < 4; i++) acc[mt][nt][i] = 0.f;

    for (int k0 = 0; k0 < 256; k0 += 32) {
        const bool left = (k0 < 128);
        // stage A: 128 rows x 32 halves = 512 uint4 copies (fp16, no convert)
#pragma unroll
        for (int i = 0; i < 2; i++) {
            int idx = t + 256 * i;
            int k8 = idx & 3, r = idx >> 2;
            int row = row0 + r;
            uint4 v = make_uint4(0, 0, 0, 0);
            if (row < nrows) {
                const __half* srcp = left ? (meanh + (size_t)row * HIDD + k0 + k8 * 8)
                                          : (hf + (size_t)row * HIDD + (k0 - 128) + k8 * 8);
                v = *(const uint4*)srcp;
            }
            *(uint4*)&As[r][k8 * 8] = v;
        }
        // stage B: 32 k x 128 cols fp32 -> fp16, 1024 float4
#pragma unroll
        for (int i = 0; i < 4; i++) {
            int idx4 = t + 256 * i;
            int c4 = idx4 & 31, kk = idx4 >> 5;
            int gk = k0 + kk;
            const float* B = left ? (Wl + (size_t)gk * HIDD) : (Wr + (size_t)(gk - 128) * HIDD);
            float4 v = *(const float4*)(B + c4 * 4);
            uint2 p;
            *(__half2*)&p.x = __floats2half2_rn(v.x, v.y);
            *(__half2*)&p.y = __floats2half2_rn(v.z, v.w);
            *(uint2*)&Bs[kk][c4 * 4] = p;
        }
        __syncthreads();

#pragma unroll
        for (int ks = 0; ks < 32; ks += 16) {
            uint32_t aF[2][4];
#pragma unroll
            for (int mt = 0; mt < 2; mt++) {
                int ar = warp_m * 32 + mt * 16 + (lane & 15);
                int ac = ks + (lane >> 4) * 8;
                ldm_x4(aF[mt], smem_u32(&As[ar][ac]));
            }
#pragma unroll
            for (int nt2 = 0; nt2 < 4; nt2++) {
                int br = ks + (lane & 15);
                int bc = warp_n * 64 + nt2 * 16 + (lane >> 4) * 8;
                uint32_t bF[4];
                ldm_x4_t(bF, smem_u32(&Bs[br][bc]));
#pragma unroll
                for (int mt = 0; mt < 2; mt++) {
                    mma_f16(acc[mt][nt2 * 2 + 0], aF[mt], bF + 0);
                    mma_f16(acc[mt][nt2 * 2 + 1], aF[mt], bF + 2);
                }
            }
        }
        __syncthreads();
    }

    const int g = lane >> 2, tg = lane & 3;
#pragma unroll
    for (int mt = 0; mt < 2; mt++) {
#pragma unroll
        for (int nt = 0; nt < 8; nt++) {
            int col = warp_n * 64 + nt * 8 + tg * 2;
            float b0 = __ldg(&bl[col]), b1 = __ldg(&bl[col + 1]);
            int row = row0 + warp_m * 32 + mt * 16 + g;
            if (row < nrows) {
                float v0 = acc[mt][nt][0] + b0;
                float v1 = acc[mt][nt][1] + b1;
                if (do_relu) { v0 = fmaxf(v0, 0.f); v1 = fmaxf(v1, 0.f); }
                if (out) *(float2*)(out + (size_t)row * HIDD + col) = make_float2(v0, v1);
                if (hf_out)
                    *(__half2*)(hf_out + (size_t)row * HIDD + col) = __floats2half2_rn(v0, v1);
            }
            int row2 = row + 8;
            if (row2 < nrows) {
                float v0 = acc[mt][nt][2] + b0;
                float v1 = acc[mt][nt][3] + b1;
                if (do_relu) { v0 = fmaxf(v0, 0.f); v1 = fmaxf(v1, 0.f); }
                if (out) *(float2*)(out + (size_t)row2 * HIDD + col) = make_float2(v0, v1);
                if (hf_out)
                    *(__half2*)(hf_out + (size_t)row2 * HIDD + col) = __floats2half2_rn(v0, v1);
            }
        }
    }
}

// ================= encoder: hf_out = fp16(relu(x @ Wx + proj1[i1] + proj2[i2])) =================
__global__ __launch_bounds__(256, 2) void encoder2_kernel(
    const float* __restrict__ x, int Kx,
    const int* __restrict__ idx1, const float* __restrict__ proj1,
    const int* __restrict__ idx2, const float* __restrict__ proj2,
    const float* __restrict__ W,
    __half* __restrict__ hf_out, int nrows)
{
    __shared__ __align__(16) __half As[128][40];
    __shared__ __align__(16) __half Bs[32][136];

    const int t = threadIdx.x;
    const int lane = t & 31;
    const int wid = t >> 5;
    const int warp_m = wid & 3;
    const int warp_n = wid >> 2;
    const int row0 = blockIdx.x * 128;

    float acc[2][8][4];
#pragma unroll
    for (int mt = 0; mt < 2; mt++)
#pragma unroll
        for (int nt = 0; nt < 8; nt++)
#pragma unroll
            for (int i = 0; i < 4; i++) acc[mt][nt][i] = 0.f;

    for (int k0 = 0; k0 < Kx; k0 += 32) {
        // stage A: fp32 x -> fp16, 128 rows x 32 k = 1024 float4
#pragma unroll
        for (int i = 0; i < 4; i++) {
            int idx4 = t + 256 * i;
            int k4 = idx4 & 7, r = idx4 >> 3;
            int row = row0 + r;
            float4 v = make_float4(0.f, 0.f, 0.f, 0.f);
            if (row < nrows) v = *(const float4*)(x + (size_t)row * Kx + k0 + k4 * 4);
            uint2 p;
            *(__half2*)&p.x = __floats2half2_rn(v.x, v.y);
            *(__half2*)&p.y = __floats2half2_rn(v.z, v.w);
            *(uint2*)&As[r][k4 * 4] = p;
        }
#pragma unroll
        for (int i = 0; i < 4; i++) {
            int idx4 = t + 256 * i;
            int c4 = idx4 & 31, kk = idx4 >> 5;
            float4 v = *(const float4*)(W + (size_t)(k0 + kk) * HIDD + c4 * 4);
            uint2 p;
            *(__half2*)&p.x = __floats2half2_rn(v.x, v.y);
            *(__half2*)&p.y = __floats2half2_rn(v.z, v.w);
            *(uint2*)&Bs[kk][c4 * 4] = p;
        }
        __syncthreads();

#pragma unroll
        for (int ks = 0; ks < 32; ks += 16) {
            uint32_t aF[2][4];
#pragma unroll
            for (int mt = 0; mt < 2; mt++) {
                int ar = warp_m * 32 + mt * 16 + (lane & 15);
                int ac = ks + (lane >> 4) * 8;
                ldm_x4(aF[mt], smem_u32(&As[ar][ac]));
            }
#pragma unroll
            for (int nt2 = 0; nt2 < 4; nt2++) {
                int br = ks + (lane & 15);
                int bc = warp_n * 64 + nt2 * 16 + (lane >> 4) * 8;
                uint32_t bF[4];
                ldm_x4_t(bF, smem_u32(&Bs[br][bc]));
#pragma unroll
                for (int mt = 0; mt < 2; mt++) {
                    mma_f16(acc[mt][nt2 * 2 + 0], aF[mt], bF + 0);
                    mma_f16(acc[mt][nt2 * 2 + 1], aF[mt], bF + 2);
                }
            }
        }
        __syncthreads();
    }

    const int g = lane >> 2, tg = lane & 3;
#pragma unroll
    for (int mt = 0; mt < 2; mt++) {
#pragma unroll
        for (int nt = 0; nt < 8; nt++) {
            int col = warp_n * 64 + nt * 8 + tg * 2;
            int row = row0 + warp_m * 32 + mt * 16 + g;
            if (row < nrows) {
                const float* p1 = proj1 + (size_t)idx1[row] * HIDD;
                float a0 = p1[col], a1 = p1[col + 1];
                if (idx2) {
                    const float* p2 = proj2 + (size_t)idx2[row] * HIDD;
                    a0 += p2[col]; a1 += p2[col + 1];
                }
                float v0 = fmaxf(acc[mt][nt][0] + a0, 0.f);
                float v1 = fmaxf(acc[mt][nt][1] + a1, 0.f);
                *(__half2*)(hf_out + (size_t)row * HIDD + col) = __floats2half2_rn(v0, v1);
            }
            int row2 = row + 8;
            if (row2 < nrows) {
                const float* p1 = proj1 + (size_t)idx1[row2] * HIDD;
                float a0 = p1[col], a1 = p1[col + 1];
                if (idx2) {
                    const float* p2 = proj2 + (size_t)idx2[row2] * HIDD;
                    a0 += p2[col]; a1 += p2[col + 1];
                }
                float v0 = fmaxf(acc[mt][nt][2] + a0, 0.f);
                float v1 = fmaxf(acc[mt][nt][3] + a1, 0.f);
                *(__half2*)(hf_out + (size_t)row2 * HIDD + col) = __floats2half2_rn(v0, v1);
            }
        }
    }
}

// ---------------- launch ----------------
extern "C" void kernel_launch(void* const* d_in, const int* in_sizes, int n_in,
                              void* d_out, int out_size) {
    const float* x_pol    = (const float*)d_in[0];
    const int*   pol_sidx = (const int*)d_in[1];
    const float* x_comp   = (const float*)d_in[2];
    const int*   c_sidx   = (const int*)d_in[3];
    const int*   c_iidx   = (const int*)d_in[4];
    const int*   edge     = (const int*)d_in[5];
    const float* st_emb   = (const float*)d_in[6];
    const float* sec_emb  = (const float*)d_in[7];
    const float* ind_emb  = (const float*)d_in[8];
    const float* W_pol    = (const float*)d_in[9];
    const float* b_pol    = (const float*)d_in[10];
    const float* W_comp   = (const float*)d_in[11];
    const float* b_comp   = (const float*)d_in[12];
    const float* Wl1      = (const float*)d_in[13];
    const float* bl1      = (const float*)d_in[14];
    const float* Wr1      = (const float*)d_in[15];
    const float* Wl2      = (const float*)d_in[16];
    const float* bl2      = (const float*)d_in[17];
    const float* Wr2      = (const float*)d_in[18];
    float* out = (float*)d_out;

    const int E = in_sizes[5] / 2;
    const int* src = edge;
    const int* dst = edge + E;

    static __half *p_hf = nullptr, *p_meanh;
    static float *p_sp, *p_secp, *p_ip;
    static int *p_cnt, *p_row, *p_cur, *p_csr, *p_blk;
    if (p_hf == nullptr) {
        cudaGetSymbolAddress((void**)&p_hf, g_hf);
        cudaGetSymbolAddress((void**)&p_meanh, g_meanh);
        cudaGetSymbolAddress((void**)&p_cnt, g_cnt_i);
        cudaGetSymbolAddress((void**)&p_row, g_row);
        cudaGetSymbolAddress((void**)&p_cur, g_cur);
        cudaGetSymbolAddress((void**)&p_csr, g_csr);
        cudaGetSymbolAddress((void**)&p_blk, g_blk);
        cudaGetSymbolAddress((void**)&p_sp, g_sproj);
        cudaGetSymbolAddress((void**)&p_secp, g_secproj);
        cudaGetSymbolAddress((void**)&p_ip, g_iproj);
    }

    const int NB = (NN + 255) / 256;  // 391

    // ---- CSR build (shared by both layers) ----
    cudaMemsetAsync(p_cnt, 0, NN * sizeof(int));
    count_int_kernel<<<(E + 255) / 256, 256>>>(dst, p_cnt, E);
    blk_reduce_kernel<<<NB, 256>>>(p_cnt, p_blk, NN);
    scan_blk_kernel<<<1, 32>>>(p_blk, NB);
    blk_scan_write_kernel<<<NB, 256>>>(p_cnt, p_blk, p_row, p_cur, NN);
    fill_csr_kernel<<<(E + 255) / 256, 256>>>(src, dst, p_cur, p_csr, E);

    // ---- embedding projections + encoders -> g_hf ----
    embproj_kernel<<<(27136 + 255) / 256, 256>>>(st_emb, sec_emb, ind_emb,
                                                 W_pol, b_pol, W_comp, b_comp,
                                                 p_sp, p_secp, p_ip);
    encoder2_kernel<<<(NP + 127) / 128, 256>>>(x_pol, 64, pol_sidx, p_sp,
                                               (const int*)nullptr, (const float*)nullptr,
                                               W_pol, p_hf, NP);
    encoder2_kernel<<<(NC + 127) / 128, 256>>>(x_comp, 96, c_sidx, p_secp,
                                               c_iidx, p_ip,
                                               W_comp, p_hf + (size_t)NP * HIDD, NC);

    // ---- SAGE layer 1 (writes new g_hf) ----
    gather_mean_kernel<<<(NN * 32 + 255) / 256, 256>>>(p_hf, p_meanh);
    sage_mma_kernel<<<(NN + 127) / 128, 256>>>(p_meanh, p_hf, Wl1, bl1, Wr1,
                                               (float*)nullptr, p_hf, NN, 1);

    // ---- SAGE layer 2 (writes fp32 d_out) ----
    gather_mean_kernel<<<(NN * 32 + 255) / 256, 256>>>(p_hf, p_meanh);
    sage_mma_kernel<<<(NN + 127) / 128, 256>>>(p_meanh, p_hf, Wl2, bl2, Wr2,
                                               out, (__half*)nullptr, NN, 0);
}

// round 11
// speedup vs baseline: 4.0681x; 1.0543x over previous
#include <cuda_runtime.h>
#include <cuda_fp16.h>
#include <cstdint>

#define NP 20000
#define NC 80000
#define NN 100000
#define HIDD 128
#define EMAX 1600000

// ---------------- scratch (static device globals; no allocation) ----------------
__device__ __half g_hf[(size_t)NN * HIDD];     // current layer features (fp16)
__device__ __half g_meanh[(size_t)NN * HIDD];  // aggregated mean per node (fp16)
__device__ int    g_cnt_i[NN];                 // in-degree
__device__ int    g_row[NN];                   // CSR row starts
__device__ int    g_cur[NN];                   // fill cursors
__device__ int    g_csr[EMAX];                 // CSR src ids
__device__ int    g_blk[512];                  // block sums for scan
__device__ float  g_sproj[50 * HIDD];
__device__ float  g_secproj[12 * HIDD];
__device__ float  g_iproj[150 * HIDD];

// ---------------- helpers ----------------
__device__ __forceinline__ uint32_t smem_u32(const void* p) {
    return (uint32_t)__cvta_generic_to_shared(p);
}
__device__ __forceinline__ void ldm_x4(uint32_t* r, uint32_t addr) {
    asm volatile("ldmatrix.sync.aligned.m8n8.x4.shared.b16 {%0,%1,%2,%3},[%4];"
                 : "=r"(r[0]), "=r"(r[1]), "=r"(r[2]), "=r"(r[3]) : "r"(addr));
}
__device__ __forceinline__ void ldm_x4_t(uint32_t* r, uint32_t addr) {
    asm volatile("ldmatrix.sync.aligned.m8n8.x4.trans.shared.b16 {%0,%1,%2,%3},[%4];"
                 : "=r"(r[0]), "=r"(r[1]), "=r"(r[2]), "=r"(r[3]) : "r"(addr));
}
__device__ __forceinline__ void mma_f16(float* d, const uint32_t* a, const uint32_t* b) {
    asm volatile("mma.sync.aligned.m16n8k16.row.col.f32.f16.f16.f32 "
                 "{%0,%1,%2,%3},{%4,%5,%6,%7},{%8,%9},{%0,%1,%2,%3};"
                 : "+f"(d[0]), "+f"(d[1]), "+f"(d[2]), "+f"(d[3])
                 : "r"(a[0]), "r"(a[1]), "r"(a[2]), "r"(a[3]), "r"(b[0]), "r"(b[1]));
}

// ---------------- CSR build ----------------
__global__ void count_int_kernel(const int* __restrict__ dst, int* cnt, int E) {
    int e = blockIdx.x * blockDim.x + threadIdx.x;
    if (e < E) atomicAdd(&cnt[dst[e]], 1);
}
__global__ void blk_reduce_kernel(const int* __restrict__ cnt, int* blk, int n) {
    __shared__ int s[256];
    int idx = blockIdx.x * 256 + threadIdx.x;
    s[threadIdx.x] = (idx < n) ? cnt[idx] : 0;
    __syncthreads();
    for (int off = 128; off > 0; off >>= 1) {
        if (threadIdx.x < off) s[threadIdx.x] += s[threadIdx.x + off];
        __syncthreads();
    }
    if (threadIdx.x == 0) blk[blockIdx.x] = s[0];
}
// parallel exclusive scan of nb (<=512) block sums, single block of 512
__global__ void scan_blk_kernel(int* blk, int nb) {
    __shared__ int s[512];
    int t = threadIdx.x;
    int v = (t < nb) ? blk[t] : 0;
    s[t] = v;
    __syncthreads();
#pragma unroll
    for (int off = 1; off < 512; off <<= 1) {
        int x = (t >= off) ? s[t - off] : 0;
        __syncthreads();
        s[t] += x;
        __syncthreads();
    }
    if (t < nb) blk[t] = s[t] - v;  // exclusive
}
__global__ void blk_scan_write_kernel(const int* __restrict__ cnt, const int* __restrict__ blk,
                                      int* row, int* cur, int n) {
    __shared__ int s[256];
    int t = threadIdx.x;
    int idx = blockIdx.x * 256 + t;
    int v = (idx < n) ? cnt[idx] : 0;
    s[t] = v;
    __syncthreads();
#pragma unroll
    for (int off = 1; off < 256; off <<= 1) {
        int x = (t >= off) ? s[t - off] : 0;
        __syncthreads();
        s[t] += x;
        __syncthreads();
    }
    if (idx < n) {
        int excl = s[t] - v + blk[blockIdx.x];
        row[idx] = excl;
        cur[idx] = excl;
    }
}
__global__ void fill_csr_kernel(const int* __restrict__ src, const int* __restrict__ dst,
                                int* cur, int* csr, int E) {
    int e = blockIdx.x * blockDim.x + threadIdx.x;
    if (e < E) {
        int slot = atomicAdd(&cur[dst[e]], 1);
        csr[slot] = src[e];
    }
}

// ---------------- half-warp-per-node gather + mean (fp16, uint4 lanes) ----------------
__global__ __launch_bounds__(256) void gather_mean_kernel(const __half* __restrict__ hsrc,
                                                          __half* __restrict__ mout) {
    int gtid = blockIdx.x * blockDim.x + threadIdx.x;
    int node = gtid >> 4;         // 16 lanes per node
    int lane = threadIdx.x & 15;  // lane*8 halves -> uint4
    if (node >= NN) return;
    int beg = g_row[node];
    int n = g_cnt_i[node];
    float acc[8] = {0.f, 0.f, 0.f, 0.f, 0.f, 0.f, 0.f, 0.f};
    const size_t off = (size_t)lane * 8;
    int i = 0;
    for (; i + 4 <= n; i += 4) {
        int s0 = __ldg(&g_csr[beg + i + 0]);
        int s1 = __ldg(&g_csr[beg + i + 1]);
        int s2 = __ldg(&g_csr[beg + i + 2]);
        int s3 = __ldg(&g_csr[beg + i + 3]);
        uint4 u0 = *(const uint4*)(hsrc + (size_t)s0 * HIDD + off);
        uint4 u1 = *(const uint4*)(hsrc + (size_t)s1 * HIDD + off);
        uint4 u2 = *(const uint4*)(hsrc + (size_t)s2 * HIDD + off);
        uint4 u3 = *(const uint4*)(hsrc + (size_t)s3 * HIDD + off);
#pragma unroll
        for (int j = 0; j < 4; j++) {
            uint32_t w0 = (&u0.x)[j], w1 = (&u1.x)[j], w2 = (&u2.x)[j], w3 = (&u3.x)[j];
            float2 f0 = __half22float2(*(__half2*)&w0);
            float2 f1 = __half22float2(*(__half2*)&w1);
            float2 f2 = __half22float2(*(__half2*)&w2);
            float2 f3 = __half22float2(*(__half2*)&w3);
            acc[j * 2 + 0] += (f0.x + f1.x) + (f2.x + f3.x);
            acc[j * 2 + 1] += (f0.y + f1.y) + (f2.y + f3.y);
        }
    }
    for (; i < n; i++) {
        int s0 = __ldg(&g_csr[beg + i]);
        uint4 u0 = *(const uint4*)(hsrc + (size_t)s0 * HIDD + off);
#pragma unroll
        for (int j = 0; j < 4; j++) {
            uint32_t w0 = (&u0.x)[j];
            float2 f0 = __half22float2(*(__half2*)&w0);
            acc[j * 2 + 0] += f0.x;
            acc[j * 2 + 1] += f0.y;
        }
    }
    float inv = 1.f / fmaxf((float)n, 1.f);
    uint4 r;
#pragma unroll
    for (int j = 0; j < 4; j++) {
        __half2 h2 = __floats2half2_rn(acc[j * 2] * inv, acc[j * 2 + 1] * inv);
        (&r.x)[j] = *(uint32_t*)&h2;
    }
    *(uint4*)(mout + (size_t)node * HIDD + off) = r;
}

// ---------------- embedding projection tables ----------------
__global__ void embproj_kernel(const float* __restrict__ st_emb,
                               const float* __restrict__ sec_emb,
                               const float* __restrict__ ind_emb,
                               const float* __restrict__ W_pol,
                               const float* __restrict__ b_pol,
                               const float* __restrict__ W_comp,
                               const float* __restrict__ b_comp,
                               float* __restrict__ sproj, float* __restrict__ secproj,
                               float* __restrict__ iproj) {
    int i = blockIdx.x * blockDim.x + threadIdx.x;
    if (i >= 27136) return;
    const float* emb; const float* W; const float* bias; float* outp; int r, c;
    if (i < 6400) {
        r = i >> 7; c = i & 127;
        emb = st_emb + r * 8; W = W_pol + 64 * HIDD; bias = b_pol; outp = sproj + i;
    } else if (i < 7936) {
        int j = i - 6400; r = j >> 7; c = j & 127;
        emb = sec_emb + r * 8; W = W_comp + 96 * HIDD; bias = b_comp; outp = secproj + j;
    } else {
        int j = i - 7936; r = j >> 7; c = j & 127;
        emb = ind_emb + r * 8; W = W_comp + 104 * HIDD; bias = nullptr; outp = iproj + j;
    }
    float s = bias ? bias[c] : 0.f;
#pragma unroll
    for (int j = 0; j < 8; j++) s = fmaf(emb[j], W[j * HIDD + c], s);
    *outp = s;
}

// ================= single-pass fp16 SAGE GEMM =================
__global__ __launch_bounds__(256, 2) void sage_mma_kernel(
    const __half* __restrict__ meanh, const __half* __restrict__ hf,
    const float* __restrict__ Wl, const float* __restrict__ bl,
    const float* __restrict__ Wr,
    float* __restrict__ out, __half* __restrict__ hf_out, int nrows, int do_relu)
{
    __shared__ __align__(16) __half As[128][40];
    __shared__ __align__(16) __half Bs[32][136];

    const int t = threadIdx.x;
    const int lane = t & 31;
    const int wid = t >> 5;
    const int warp_m = wid & 3;
    const int warp_n = wid >> 2;
    const int row0 = blockIdx.x * 128;

    float acc[2][8][4];
#pragma unroll
    for (int mt = 0; mt < 2; mt++)
#pragma unroll
        for (int nt = 0; nt < 8; nt++)
#pragma unroll
            for (int i = 0; i < 4; i++) acc[mt][nt][i] = 0.f;

    for (int k0 = 0; k0 < 256; k0 += 32) {
        const bool left = (k0 < 128);
#pragma unroll
        for (int i = 0; i < 2; i++) {
            int idx = t + 256 * i;
            int k8 = idx & 3, r = idx >> 2;
            int row = row0 + r;
            uint4 v = make_uint4(0, 0, 0, 0);
            if (row < nrows) {
                const __half* srcp = left ? (meanh + (size_t)row * HIDD + k0 + k8 * 8)
                                          : (hf + (size_t)row * HIDD + (k0 - 128) + k8 * 8);
                v = *(const uint4*)srcp;
            }
            *(uint4*)&As[r][k8 * 8] = v;
        }
#pragma unroll
        for (int i = 0; i < 4; i++) {
            int idx4 = t + 256 * i;
            int c4 = idx4 & 31, kk = idx4 >> 5;
            int gk = k0 + kk;
            const float* B = left ? (Wl + (size_t)gk * HIDD) : (Wr + (size_t)(gk - 128) * HIDD);
            float4 v = *(const float4*)(B + c4 * 4);
            uint2 p;
            *(__half2*)&p.x = __floats2half2_rn(v.x, v.y);
            *(__half2*)&p.y = __floats2half2_rn(v.z, v.w);
            *(uint2*)&Bs[kk][c4 * 4] = p;
        }
        __syncthreads();

#pragma unroll
        for (int ks = 0; ks < 32; ks += 16) {
            uint32_t aF[2][4];
#pragma unroll
            for (int mt = 0; mt < 2; mt++) {
                int ar = warp_m * 32 + mt * 16 + (lane & 15);
                int ac = ks + (lane >> 4) * 8;
                ldm_x4(aF[mt], smem_u32(&As[ar][ac]));
            }
#pragma unroll
            for (int nt2 = 0; nt2 < 4; nt2++) {
                int br = ks + (lane & 15);
                int bc = warp_n * 64 + nt2 * 16 + (lane >> 4) * 8;
                uint32_t bF[4];
                ldm_x4_t(bF, smem_u32(&Bs[br][bc]));
#pragma unroll
                for (int mt = 0; mt < 2; mt++) {
                    mma_f16(acc[mt][nt2 * 2 + 0], aF[mt], bF + 0);
                    mma_f16(acc[mt][nt2 * 2 + 1], aF[mt], bF + 2);
                }
            }
        }
        __syncthreads();
    }

    const int g = lane >> 2, tg = lane & 3;
#pragma unroll
    for (int mt = 0; mt < 2; mt++) {
#pragma unroll
        for (int nt = 0; nt < 8; nt++) {
            int col = warp_n * 64 + nt * 8 + tg * 2;
            float b0 = __ldg(&bl[col]), b1 = __ldg(&bl[col + 1]);
            int row = row0 + warp_m * 32 + mt * 16 + g;
            if (row < nrows) {
                float v0 = acc[mt][nt][0] + b0;
                float v1 = acc[mt][nt][1] + b1;
                if (do_relu) { v0 = fmaxf(v0, 0.f); v1 = fmaxf(v1, 0.f); }
                if (out) *(float2*)(out + (size_t)row * HIDD + col) = make_float2(v0, v1);
                if (hf_out)
                    *(__half2*)(hf_out + (size_t)row * HIDD + col) = __floats2half2_rn(v0, v1);
            }
            int row2 = row + 8;
            if (row2 < nrows) {
                float v0 = acc[mt][nt][2] + b0;
                float v1 = acc[mt][nt][3] + b1;
                if (do_relu) { v0 = fmaxf(v0, 0.f); v1 = fmaxf(v1, 0.f); }
                if (out) *(float2*)(out + (size_t)row2 * HIDD + col) = make_float2(v0, v1);
                if (hf_out)
                    *(__half2*)(hf_out + (size_t)row2 * HIDD + col) = __floats2half2_rn(v0, v1);
            }
        }
    }
}

// ================= encoder: hf_out = fp16(relu(x @ Wx + proj1[i1] + proj2[i2])) =================
__global__ __launch_bounds__(256, 2) void encoder2_kernel(
    const float* __restrict__ x, int Kx,
    const int* __restrict__ idx1, const float* __restrict__ proj1,
    const int* __restrict__ idx2, const float* __restrict__ proj2,
    const float* __restrict__ W,
    __half* __restrict__ hf_out, int nrows)
{
    __shared__ __align__(16) __half As[128][40];
    __shared__ __align__(16) __half Bs[32][136];

    const int t = threadIdx.x;
    const int lane = t & 31;
    const int wid = t >> 5;
    const int warp_m = wid & 3;
    const int warp_n = wid >> 2;
    const int row0 = blockIdx.x * 128;

    float acc[2][8][4];
#pragma unroll
    for (int mt = 0; mt < 2; mt++)
#pragma unroll
        for (int nt = 0; nt < 8; nt++)
#pragma unroll
            for (int i = 0; i < 4; i++) acc[mt][nt][i] = 0.f;

    for (int k0 = 0; k0 < Kx; k0 += 32) {
#pragma unroll
        for (int i = 0; i < 4; i++) {
            int idx4 = t + 256 * i;
            int k4 = idx4 & 7, r = idx4 >> 3;
            int row = row0 + r;
            float4 v = make_float4(0.f, 0.f, 0.f, 0.f);
            if (row < nrows) v = *(const float4*)(x + (size_t)row * Kx + k0 + k4 * 4);
            uint2 p;
            *(__half2*)&p.x = __floats2half2_rn(v.x, v.y);
            *(__half2*)&p.y = __floats2half2_rn(v.z, v.w);
            *(uint2*)&As[r][k4 * 4] = p;
        }
#pragma unroll
        for (int i = 0; i < 4; i++) {
            int idx4 = t + 256 * i;
            int c4 = idx4 & 31, kk = idx4 >> 5;
            float4 v = *(const float4*)(W + (size_t)(k0 + kk) * HIDD + c4 * 4);
            uint2 p;
            *(__half2*)&p.x = __floats2half2_rn(v.x, v.y);
            *(__half2*)&p.y = __floats2half2_rn(v.z, v.w);
            *(uint2*)&Bs[kk][c4 * 4] = p;
        }
        __syncthreads();

#pragma unroll
        for (int ks = 0; ks < 32; ks += 16) {
            uint32_t aF[2][4];
#pragma unroll
            for (int mt = 0; mt < 2; mt++) {
                int ar = warp_m * 32 + mt * 16 + (lane & 15);
                int ac = ks + (lane >> 4) * 8;
                ldm_x4(aF[mt], smem_u32(&As[ar][ac]));
            }
#pragma unroll
            for (int nt2 = 0; nt2 < 4; nt2++) {
                int br = ks + (lane & 15);
                int bc = warp_n * 64 + nt2 * 16 + (lane >> 4) * 8;
                uint32_t bF[4];
                ldm_x4_t(bF, smem_u32(&Bs[br][bc]));
#pragma unroll
                for (int mt = 0; mt < 2; mt++) {
                    mma_f16(acc[mt][nt2 * 2 + 0], aF[mt], bF + 0);
                    mma_f16(acc[mt][nt2 * 2 + 1], aF[mt], bF + 2);
                }
            }
        }
        __syncthreads();
    }

    const int g = lane >> 2, tg = lane & 3;
#pragma unroll
    for (int mt = 0; mt < 2; mt++) {
#pragma unroll
        for (int nt = 0; nt < 8; nt++) {
            int col = warp_n * 64 + nt * 8 + tg * 2;
            int row = row0 + warp_m * 32 + mt * 16 + g;
            if (row < nrows) {
                const float* p1 = proj1 + (size_t)idx1[row] * HIDD;
                float a0 = p1[col], a1 = p1[col + 1];
                if (idx2) {
                    const float* p2 = proj2 + (size_t)idx2[row] * HIDD;
                    a0 += p2[col]; a1 += p2[col + 1];
                }
                float v0 = fmaxf(acc[mt][nt][0] + a0, 0.f);
                float v1 = fmaxf(acc[mt][nt][1] + a1, 0.f);
                *(__half2*)(hf_out + (size_t)row * HIDD + col) = __floats2half2_rn(v0, v1);
            }
            int row2 = row + 8;
            if (row2 < nrows) {
                const float* p1 = proj1 + (size_t)idx1[row2] * HIDD;
                float a0 = p1[col], a1 = p1[col + 1];
                if (idx2) {
                    const float* p2 = proj2 + (size_t)idx2[row2] * HIDD;
                    a0 += p2[col]; a1 += p2[col + 1];
                }
                float v0 = fmaxf(acc[mt][nt][2] + a0, 0.f);
                float v1 = fmaxf(acc[mt][nt][3] + a1, 0.f);
                *(__half2*)(hf_out + (size_t)row2 * HIDD + col) = __floats2half2_rn(v0, v1);
            }
        }
    }
}

// ---------------- launch ----------------
extern "C" void kernel_launch(void* const* d_in, const int* in_sizes, int n_in,
                              void* d_out, int out_size) {
    const float* x_pol    = (const float*)d_in[0];
    const int*   pol_sidx = (const int*)d_in[1];
    const float* x_comp   = (const float*)d_in[2];
    const int*   c_sidx   = (const int*)d_in[3];
    const int*   c_iidx   = (const int*)d_in[4];
    const int*   edge     = (const int*)d_in[5];
    const float* st_emb   = (const float*)d_in[6];
    const float* sec_emb  = (const float*)d_in[7];
    const float* ind_emb  = (const float*)d_in[8];
    const float* W_pol    = (const float*)d_in[9];
    const float* b_pol    = (const float*)d_in[10];
    const float* W_comp   = (const float*)d_in[11];
    const float* b_comp   = (const float*)d_in[12];
    const float* Wl1      = (const float*)d_in[13];
    const float* bl1      = (const float*)d_in[14];
    const float* Wr1      = (const float*)d_in[15];
    const float* Wl2      = (const float*)d_in[16];
    const float* bl2      = (const float*)d_in[17];
    const float* Wr2      = (const float*)d_in[18];
    float* out = (float*)d_out;

    const int E = in_sizes[5] / 2;
    const int* src = edge;
    const int* dst = edge + E;

    static __half *p_hf = nullptr, *p_meanh;
    static float *p_sp, *p_secp, *p_ip;
    static int *p_cnt, *p_row, *p_cur, *p_csr, *p_blk;
    static cudaStream_t s2 = nullptr;
    static cudaEvent_t evF = nullptr, evJ = nullptr;
    if (p_hf == nullptr) {
        cudaGetSymbolAddress((void**)&p_hf, g_hf);
        cudaGetSymbolAddress((void**)&p_meanh, g_meanh);
        cudaGetSymbolAddress((void**)&p_cnt, g_cnt_i);
        cudaGetSymbolAddress((void**)&p_row, g_row);
        cudaGetSymbolAddress((void**)&p_cur, g_cur);
        cudaGetSymbolAddress((void**)&p_csr, g_csr);
        cudaGetSymbolAddress((void**)&p_blk, g_blk);
        cudaGetSymbolAddress((void**)&p_sp, g_sproj);
        cudaGetSymbolAddress((void**)&p_secp, g_secproj);
        cudaGetSymbolAddress((void**)&p_ip, g_iproj);
        cudaStreamCreateWithFlags(&s2, cudaStreamNonBlocking);
        cudaEventCreateWithFlags(&evF, cudaEventDisableTiming);
        cudaEventCreateWithFlags(&evJ, cudaEventDisableTiming);
    }

    const int NB = (NN + 255) / 256;  // 391

    // ---- fork: CSR build on s2, encoders on main stream (independent data) ----
    cudaEventRecord(evF, 0);
    cudaStreamWaitEvent(s2, evF, 0);

    // CSR chain on s2
    cudaMemsetAsync(p_cnt, 0, NN * sizeof(int), s2);
    count_int_kernel<<<(E + 255) / 256, 256, 0, s2>>>(dst, p_cnt, E);
    blk_reduce_kernel<<<NB, 256, 0, s2>>>(p_cnt, p_blk, NN);
    scan_blk_kernel<<<1, 512, 0, s2>>>(p_blk, NB);
    blk_scan_write_kernel<<<NB, 256, 0, s2>>>(p_cnt, p_blk, p_row, p_cur, NN);
    fill_csr_kernel<<<(E + 255) / 256, 256, 0, s2>>>(src, dst, p_cur, p_csr, E);
    cudaEventRecord(evJ, s2);

    // encoder chain on main stream
    embproj_kernel<<<(27136 + 255) / 256, 256>>>(st_emb, sec_emb, ind_emb,
                                                 W_pol, b_pol, W_comp, b_comp,
                                                 p_sp, p_secp, p_ip);
    encoder2_kernel<<<(NP + 127) / 128, 256>>>(x_pol, 64, pol_sidx, p_sp,
                                               (const int*)nullptr, (const float*)nullptr,
                                               W_pol, p_hf, NP);
    encoder2_kernel<<<(NC + 127) / 128, 256>>>(x_comp, 96, c_sidx, p_secp,
                                               c_iidx, p_ip,
                                               W_comp, p_hf + (size_t)NP * HIDD, NC);

    // ---- join ----
    cudaStreamWaitEvent(0, evJ, 0);

    // ---- SAGE layer 1 (writes new g_hf) ----
    gather_mean_kernel<<<(NN * 16 + 255) / 256, 256>>>(p_hf, p_meanh);
    sage_mma_kernel<<<(NN + 127) / 128, 256>>>(p_meanh, p_hf, Wl1, bl1, Wr1,
                                               (float*)nullptr, p_hf, NN, 1);

    // ---- SAGE layer 2 (writes fp32 d_out) ----
    gather_mean_kernel<<<(NN * 16 + 255) / 256, 256>>>(p_hf, p_meanh);
    sage_mma_kernel<<<(NN + 127) / 128, 256>>>(p_meanh, p_hf, Wl2, bl2, Wr2,
                                               out, (__half*)nullptr, NN, 0);
}